// round 1
// baseline (speedup 1.0000x reference)
#include <cuda_runtime.h>

#define NB 1024
#define NT 240
#define NH 90
#define NF 180
#define TTILE 120
#define NTHREADS1 225

// scratch (alloc-free rule: __device__ globals)
__device__ float g_h2[(size_t)NB * NT * NH];     // [B][T][H]
__device__ float g_part[10 * NB * 40];           // k-split partial logits

static __device__ __forceinline__ float sigf(float x) {
    return __fdividef(1.f, 1.f + __expf(-x));
}
static __device__ __forceinline__ float tanh_f(float x) {
    float e = __expf(2.f * x);
    return __fdividef(e - 1.f, e + 1.f);
}
static __device__ __forceinline__ void ffma2(unsigned long long& c,
                                             unsigned long long a,
                                             unsigned long long b) {
    asm("fma.rn.f32x2 %0, %1, %2, %0;" : "+l"(c) : "l"(a), "l"(b));
}
static __device__ __forceinline__ unsigned long long pack2(float x, float y) {
    unsigned long long r;
    asm("mov.b64 %0, {%1, %2};" : "=l"(r)
        : "r"(__float_as_uint(x)), "r"(__float_as_uint(y)));
    return r;
}
static __device__ __forceinline__ float2 unpk(unsigned long long v) {
    unsigned int lo, hi;
    asm("mov.b64 {%0, %1}, %2;" : "=r"(lo), "=r"(hi) : "l"(v));
    return make_float2(__uint_as_float(lo), __uint_as_float(hi));
}

// f32x2 register-tile GEMM fragment: acc[m][jj] accumulates t-pair (30m+2tt, +1) x col (j0+jj)
template <int K, int ASTRIDE>
static __device__ __forceinline__ void gemm_tile(const float* __restrict__ A,
                                                 const float* __restrict__ W,
                                                 unsigned long long acc[4][6],
                                                 int tt, int j0) {
    const float* arow = A + 2 * tt;
    const float* wrow = W + j0;
#pragma unroll 3
    for (int k = 0; k < K; ++k) {
        unsigned long long a0 = *reinterpret_cast<const unsigned long long*>(arow);
        unsigned long long a1 = *reinterpret_cast<const unsigned long long*>(arow + 30);
        unsigned long long a2 = *reinterpret_cast<const unsigned long long*>(arow + 60);
        unsigned long long a3 = *reinterpret_cast<const unsigned long long*>(arow + 90);
#pragma unroll
        for (int jj = 0; jj < 6; ++jj) {
            float w = wrow[jj];
            unsigned long long wv = pack2(w, w);
            ffma2(acc[0][jj], a0, wv);
            ffma2(acc[1][jj], a1, wv);
            ffma2(acc[2][jj], a2, wv);
            ffma2(acc[3][jj], a3, wv);
        }
        arow += ASTRIDE;
        wrow += NH;
    }
}

// Fused encoder + decoder LSTM-cell (zero state => f-gate skipped).
// Grid: (2, 1024). Block: 225 threads (15 j-threads x 15 t-threads).
// smem: As[180][120] (86400B) | Ws[<=180][90] (64800B) | Ss[90][120] (43200B)
__global__ void __launch_bounds__(NTHREADS1, 1)
fused_lstm_kernel(const float* __restrict__ x,
                  const float* __restrict__ eW,  const float* __restrict__ eb1,
                  const float* __restrict__ eb2, const float* __restrict__ dW,
                  const float* __restrict__ db1, const float* __restrict__ db2) {
    extern __shared__ float sm[];
    float* As = sm;             // 21600 floats
    float* Ws = sm + 21600;     // 16200 floats
    float* Ss = sm + 37800;     // 10800 floats

    const int tid = threadIdx.x;
    const int b   = blockIdx.y;
    const int t0g = blockIdx.x * TTILE;
    const int jt = tid / 15, tt = tid - jt * 15;
    const int j0 = jt * 6;

    // Load x slab: xe[f][t] = x[b, f/60, f%60, t0g+t] = x[b*180*240 + f*240 + t0g + t]
    const float* xb = x + (size_t)b * (NF * NT) + t0g;
    for (int idx = tid; idx < NF * TTILE; idx += NTHREADS1) {
        int f = idx / TTILE, t = idx - f * TTILE;
        As[f * TTILE + t] = xb[f * NT + t];
    }

    const int goff[3] = {0, 180, 270};  // i, g, o gate row offsets (f skipped)

    // ===== ENCODER =====
    for (int p = 0; p < 3; ++p) {
        __syncthreads();  // protect Ws (and first time: As) before overwrite/use
        const float* wsrc = eW + goff[p] * NF;
        for (int idx = tid; idx < NH * NF; idx += NTHREADS1) {
            int j = idx / NF, k = idx - j * NF;
            Ws[k * NH + j] = wsrc[j * NF + k];
        }
        __syncthreads();

        float bias[6];
#pragma unroll
        for (int jj = 0; jj < 6; ++jj)
            bias[jj] = eb1[goff[p] + j0 + jj] + eb2[goff[p] + j0 + jj];

        unsigned long long acc[4][6];
#pragma unroll
        for (int m = 0; m < 4; ++m)
#pragma unroll
            for (int jj = 0; jj < 6; ++jj) acc[m][jj] = 0ull;

        gemm_tile<NF, TTILE>(As, Ws, acc, tt, j0);

#pragma unroll
        for (int jj = 0; jj < 6; ++jj) {
#pragma unroll
            for (int m = 0; m < 4; ++m) {
                float2 v = unpk(acc[m][jj]);
                v.x += bias[jj]; v.y += bias[jj];
                float2* sp = reinterpret_cast<float2*>(
                    Ss + (j0 + jj) * TTILE + 30 * m + 2 * tt);
                if (p == 0) {                         // i gate
                    *sp = make_float2(sigf(v.x), sigf(v.y));
                } else if (p == 1) {                  // g gate -> c = sig(i)*tanh(g)
                    float2 si = *sp;
                    *sp = make_float2(si.x * tanh_f(v.x), si.y * tanh_f(v.y));
                } else {                              // o gate -> h1 = sig(sig(o)*tanh(c))
                    float2 c = *sp;
                    *sp = make_float2(sigf(sigf(v.x) * tanh_f(c.x)),
                                      sigf(sigf(v.y) * tanh_f(c.y)));
                }
            }
        }
    }

    // ===== DECODER ===== (A = Ss (h1) [90][120]; staging S2 reuses As region)
    float* S2 = As;
    for (int p = 0; p < 3; ++p) {
        __syncthreads();
        const float* wsrc = dW + goff[p] * NH;
        for (int idx = tid; idx < NH * NH; idx += NTHREADS1) {
            int j = idx / NH, k = idx - j * NH;
            Ws[k * NH + j] = wsrc[j * NH + k];
        }
        __syncthreads();

        float bias[6];
#pragma unroll
        for (int jj = 0; jj < 6; ++jj)
            bias[jj] = db1[goff[p] + j0 + jj] + db2[goff[p] + j0 + jj];

        unsigned long long acc[4][6];
#pragma unroll
        for (int m = 0; m < 4; ++m)
#pragma unroll
            for (int jj = 0; jj < 6; ++jj) acc[m][jj] = 0ull;

        gemm_tile<NH, TTILE>(Ss, Ws, acc, tt, j0);

        if (p < 2) {
#pragma unroll
            for (int jj = 0; jj < 6; ++jj) {
#pragma unroll
                for (int m = 0; m < 4; ++m) {
                    float2 v = unpk(acc[m][jj]);
                    v.x += bias[jj]; v.y += bias[jj];
                    float2* sp = reinterpret_cast<float2*>(
                        S2 + (j0 + jj) * TTILE + 30 * m + 2 * tt);
                    if (p == 0) {
                        *sp = make_float2(sigf(v.x), sigf(v.y));
                    } else {
                        float2 si = *sp;
                        *sp = make_float2(si.x * tanh_f(v.x), si.y * tanh_f(v.y));
                    }
                }
            }
        } else {
            // h2 = sig(o) * tanh(c); write to global [b][t][j]
#pragma unroll
            for (int m = 0; m < 4; ++m) {
                float hv0[6], hv1[6];
#pragma unroll
                for (int jj = 0; jj < 6; ++jj) {
                    float2 v = unpk(acc[m][jj]);
                    v.x += bias[jj]; v.y += bias[jj];
                    float2 c = *reinterpret_cast<float2*>(
                        S2 + (j0 + jj) * TTILE + 30 * m + 2 * tt);
                    hv0[jj] = sigf(v.x) * tanh_f(c.x);
                    hv1[jj] = sigf(v.y) * tanh_f(c.y);
                }
                int t = t0g + 30 * m + 2 * tt;
                float* o0 = g_h2 + ((size_t)b * NT + t) * NH + j0;
                float* o1 = o0 + NH;
#pragma unroll
                for (int jj = 0; jj < 6; jj += 2) {
                    *reinterpret_cast<float2*>(o0 + jj) = make_float2(hv0[jj], hv0[jj + 1]);
                    *reinterpret_cast<float2*>(o1 + jj) = make_float2(hv1[jj], hv1[jj + 1]);
                }
            }
        }
    }
}

// Output GEMM: logits[b,n] partial over K-split. Grid (10 ksplit, 32 b-blocks), 256 thr.
// smem: Hs[240][33] transposed h2 tile + Wt[240][44] transposed weight tile.
__global__ void __launch_bounds__(256, 1)
out_gemm_kernel(const float* __restrict__ W) {
    extern __shared__ float sm[];
    float* Hs = sm;           // 240*33 = 7920 floats
    float* Wt = sm + 7920;    // 240*44 = 10560 floats

    const int b0 = blockIdx.y * 32;
    const int k0 = blockIdx.x * 2160;
    const int tid = threadIdx.x, wi = tid >> 5, lane = tid & 31;

    float acc[40];
#pragma unroll
    for (int n = 0; n < 40; ++n) acc[n] = 0.f;

    for (int tile = 0; tile < 9; ++tile) {
        const int kt = k0 + tile * 240;
        __syncthreads();
        for (int idx = tid; idx < 32 * 240; idx += 256) {
            int bb = idx / 240, k = idx - bb * 240;
            Hs[k * 33 + bb] = g_h2[(size_t)(b0 + bb) * 21600 + kt + k];
        }
        for (int idx = tid; idx < 40 * 240; idx += 256) {
            int n = idx / 240, k = idx - n * 240;
            Wt[k * 44 + n] = W[(size_t)n * 21600 + kt + k];
        }
        __syncthreads();
#pragma unroll 2
        for (int kk = 0; kk < 30; ++kk) {
            int k = wi * 30 + kk;
            float h = Hs[k * 33 + lane];
            const float4* wp = reinterpret_cast<const float4*>(Wt + k * 44);
#pragma unroll
            for (int n4 = 0; n4 < 10; ++n4) {
                float4 w = wp[n4];
                acc[n4 * 4 + 0] += h * w.x;
                acc[n4 * 4 + 1] += h * w.y;
                acc[n4 * 4 + 2] += h * w.z;
                acc[n4 * 4 + 3] += h * w.w;
            }
        }
    }

    __syncthreads();
    float* Rs = sm;  // reuse: 8*32*40 = 10240 floats
#pragma unroll
    for (int n = 0; n < 40; ++n) Rs[(wi * 32 + lane) * 40 + n] = acc[n];
    __syncthreads();
    for (int idx = tid; idx < 32 * 40; idx += 256) {
        int bb = idx / 40, n = idx - bb * 40;
        float s = 0.f;
#pragma unroll
        for (int w = 0; w < 8; ++w) s += Rs[(w * 32 + bb) * 40 + n];
        g_part[blockIdx.x * (NB * 40) + (b0 + bb) * 40 + n] = s;
    }
}

// Reduce k-splits + bias + grouped softmax (groups of 10). Grid 1024, block 40.
__global__ void softmax_kernel(const float* __restrict__ ob, float* __restrict__ out) {
    __shared__ float L[40];
    __shared__ float E[40];
    const int b = blockIdx.x, n = threadIdx.x;
    float s = 0.f;
#pragma unroll
    for (int ks = 0; ks < 10; ++ks) s += g_part[ks * (NB * 40) + b * 40 + n];
    s += ob[n];
    L[n] = s;
    __syncthreads();
    const int g0 = (n / 10) * 10;
    float mx = -1e30f;
#pragma unroll
    for (int i = 0; i < 10; ++i) mx = fmaxf(mx, L[g0 + i]);
    float e = __expf(s - mx);
    E[n] = e;
    __syncthreads();
    float sum = 0.f;
#pragma unroll
    for (int i = 0; i < 10; ++i) sum += E[g0 + i];
    out[b * 40 + n] = __fdividef(e, sum);
}

extern "C" void kernel_launch(void* const* d_in, const int* in_sizes, int n_in,
                              void* d_out, int out_size) {
    const float* x   = (const float*)d_in[0];
    const float* eW  = (const float*)d_in[1];
    const float* eb1 = (const float*)d_in[2];
    const float* eb2 = (const float*)d_in[3];
    const float* dW  = (const float*)d_in[4];
    const float* db1 = (const float*)d_in[5];
    const float* db2 = (const float*)d_in[6];
    const float* oW  = (const float*)d_in[7];
    const float* ob  = (const float*)d_in[8];
    float* out = (float*)d_out;

    cudaFuncSetAttribute(fused_lstm_kernel,
                         cudaFuncAttributeMaxDynamicSharedMemorySize, 194400);
    cudaFuncSetAttribute(out_gemm_kernel,
                         cudaFuncAttributeMaxDynamicSharedMemorySize, 73920);

    fused_lstm_kernel<<<dim3(2, NB), NTHREADS1, 194400>>>(x, eW, eb1, eb2, dW, db1, db2);
    out_gemm_kernel<<<dim3(10, 32), 256, 73920>>>(oW);
    softmax_kernel<<<NB, 40>>>(ob, out);
}

// round 2
// speedup vs baseline: 1.1442x; 1.1442x over previous
#include <cuda_runtime.h>

#define NB 1024
#define NT 240
#define NH 90
#define NF 180
#define SSTR 244          // padded Ss row stride (conflict-aware)
#define NTHR 480

typedef unsigned long long ull;

// scratch (alloc-free rule: __device__ globals)
__device__ float g_h2[(size_t)NB * NT * NH];     // [B][T][H]
__device__ float g_part[10 * NB * 40];           // k-split partial logits

static __device__ __forceinline__ float sigf(float x) {
    return __fdividef(1.f, 1.f + __expf(-x));
}
static __device__ __forceinline__ float tanh_f(float x) {
    float e = __expf(2.f * x);
    return __fdividef(e - 1.f, e + 1.f);
}
static __device__ __forceinline__ void ffma2(ull& c, ull a, ull b) {
    asm("fma.rn.f32x2 %0, %1, %2, %0;" : "+l"(c) : "l"(a), "l"(b));
}
static __device__ __forceinline__ ull pack2(float x, float y) {
    ull r;
    asm("mov.b64 %0, {%1, %2};" : "=l"(r)
        : "r"(__float_as_uint(x)), "r"(__float_as_uint(y)));
    return r;
}
static __device__ __forceinline__ float2 unpk(ull v) {
    unsigned int lo, hi;
    asm("mov.b64 {%0, %1}, %2;" : "=r"(lo), "=r"(hi) : "l"(v));
    return make_float2(__uint_as_float(lo), __uint_as_float(hi));
}

// Per-warp tile: 6 j-cols (warp-uniform, broadcast w) x 8 t per lane (4 f32x2 pairs).
// arow pre-offset by lane (tb floats); wrow pre-offset by j0.
template <int K, int ASTR>
static __device__ __forceinline__ void gemm_block(const float* __restrict__ arow,
                                                  const float* __restrict__ wrow,
                                                  ull acc[4][6]) {
#pragma unroll 6
    for (int k = 0; k < K; ++k) {
        float4 aA = *reinterpret_cast<const float4*>(arow);
        float4 aB = *reinterpret_cast<const float4*>(arow + 4);
        ull a0 = pack2(aA.x, aA.y), a1 = pack2(aA.z, aA.w);
        ull a2 = pack2(aB.x, aB.y), a3 = pack2(aB.z, aB.w);
        float2 w01 = *reinterpret_cast<const float2*>(wrow);
        float2 w23 = *reinterpret_cast<const float2*>(wrow + 2);
        float2 w45 = *reinterpret_cast<const float2*>(wrow + 4);
        float wcol[6] = {w01.x, w01.y, w23.x, w23.y, w45.x, w45.y};
#pragma unroll
        for (int jj = 0; jj < 6; ++jj) {
            ull wv = pack2(wcol[jj], wcol[jj]);
            ffma2(acc[0][jj], a0, wv);
            ffma2(acc[1][jj], a1, wv);
            ffma2(acc[2][jj], a2, wv);
            ffma2(acc[3][jj], a3, wv);
        }
        arow += ASTR;
        wrow += NH;
    }
}

// smem layout (floats):
//  Ss  [0,      21960)  h1 / final h2 staging, 90 x SSTR
//  As  [21960,  36360)  encoder x k-chunk, 60 x 240
//  Ws  [36360,  52560)  encoder W^T chunk-major, 180 x 90
//  S2  [21960,  43560)  decoder i/c staging, 90 x 240 (reuses As+Ws-head)
//  Wd  [44460,  52560)  decoder W^T, 90 x 90 (tail of Ws region)
#define OFF_SS 0
#define OFF_AS 21960
#define OFF_WS 36360
#define OFF_S2 21960
#define OFF_WD 44460
#define SMEM_FLOATS 52560

__global__ void __launch_bounds__(NTHR, 1)
fused_lstm_kernel(const float* __restrict__ x,
                  const float* __restrict__ eW,  const float* __restrict__ eb1,
                  const float* __restrict__ eb2, const float* __restrict__ dW,
                  const float* __restrict__ db1, const float* __restrict__ db2) {
    extern __shared__ float sm[];
    float* Ss = sm + OFF_SS;
    float* As = sm + OFF_AS;
    float* Ws = sm + OFF_WS;
    float* S2 = sm + OFF_S2;
    float* Wd = sm + OFF_WD;

    const int tid  = threadIdx.x;
    const int wid  = tid >> 5;
    const int lane = tid & 31;
    const int b    = blockIdx.x;
    const int j0   = wid * 6;
    const bool act = lane < 30;
    const int tb   = lane * 8;

    const float* xb = x + (size_t)b * (NF * NT);
    const int goff[3] = {0, 180, 270};  // i, g, o rows (f skipped: c0=0)

    // ===== ENCODER (K=180, streamed in 3 chunks of 60) =====
    for (int p = 0; p < 3; ++p) {
        float bias[6];
#pragma unroll
        for (int jj = 0; jj < 6; ++jj)
            bias[jj] = eb1[goff[p] + j0 + jj] + eb2[goff[p] + j0 + jj];

        __syncthreads();  // previous pass's Ws readers done
        {
            const float* wsrc = eW + goff[p] * NF;
            for (int idx = tid; idx < NH * NF; idx += NTHR) {
                int j = idx / NF, k = idx - j * NF;
                Ws[k * NH + j] = wsrc[j * NF + k];
            }
        }

        ull acc[4][6];
#pragma unroll
        for (int m = 0; m < 4; ++m)
#pragma unroll
            for (int jj = 0; jj < 6; ++jj) acc[m][jj] = 0ull;

        for (int kc = 0; kc < 3; ++kc) {
            __syncthreads();  // prior chunk readers done (kc=0: nothing pending)
            const float4* src = reinterpret_cast<const float4*>(xb + kc * 14400);
            float4* dst = reinterpret_cast<float4*>(As);
            for (int i = tid; i < 3600; i += NTHR) dst[i] = src[i];
            __syncthreads();  // publish As chunk (and Ws on kc=0)
            if (act)
                gemm_block<60, NT>(As + tb, Ws + kc * 60 * NH + j0, acc);
        }

        if (act) {
#pragma unroll
            for (int m = 0; m < 4; ++m) {
#pragma unroll
                for (int jj = 0; jj < 6; ++jj) {
                    float2 v = unpk(acc[m][jj]);
                    v.x += bias[jj]; v.y += bias[jj];
                    float2* sp = reinterpret_cast<float2*>(
                        Ss + (j0 + jj) * SSTR + tb + 2 * m);
                    if (p == 0) {                       // i
                        *sp = make_float2(sigf(v.x), sigf(v.y));
                    } else if (p == 1) {                // g -> c = sig(i)*tanh(g)
                        float2 si = *sp;
                        *sp = make_float2(si.x * tanh_f(v.x), si.y * tanh_f(v.y));
                    } else {                            // o -> h1 = sig(sig(o)*tanh(c))
                        float2 c = *sp;
                        *sp = make_float2(sigf(sigf(v.x) * tanh_f(c.x)),
                                          sigf(sigf(v.y) * tanh_f(c.y)));
                    }
                }
            }
        }
    }

    // ===== DECODER (K=90, A = Ss resident) =====
    for (int p = 0; p < 3; ++p) {
        float bias[6];
#pragma unroll
        for (int jj = 0; jj < 6; ++jj)
            bias[jj] = db1[goff[p] + j0 + jj] + db2[goff[p] + j0 + jj];

        __syncthreads();  // prior gemm readers of Wd done; encoder Ss writes done
        {
            const float* wsrc = dW + goff[p] * NH;
            for (int idx = tid; idx < NH * NH; idx += NTHR) {
                int j = idx / NH, k = idx - j * NH;
                Wd[k * NH + j] = wsrc[j * NH + k];
            }
        }
        __syncthreads();  // publish Wd

        ull acc[4][6];
#pragma unroll
        for (int m = 0; m < 4; ++m)
#pragma unroll
            for (int jj = 0; jj < 6; ++jj) acc[m][jj] = 0ull;

        if (act) gemm_block<90, SSTR>(Ss + tb, Wd + j0, acc);

        if (p < 2) {
            if (act) {
#pragma unroll
                for (int m = 0; m < 4; ++m) {
#pragma unroll
                    for (int jj = 0; jj < 6; ++jj) {
                        float2 v = unpk(acc[m][jj]);
                        v.x += bias[jj]; v.y += bias[jj];
                        float2* sp = reinterpret_cast<float2*>(
                            S2 + (j0 + jj) * NT + tb + 2 * m);
                        if (p == 0) {
                            *sp = make_float2(sigf(v.x), sigf(v.y));
                        } else {
                            float2 si = *sp;
                            *sp = make_float2(si.x * tanh_f(v.x),
                                              si.y * tanh_f(v.y));
                        }
                    }
                }
            }
        } else {
            __syncthreads();  // all gemm reads of Ss complete before overwrite
            if (act) {
#pragma unroll
                for (int m = 0; m < 4; ++m) {
#pragma unroll
                    for (int jj = 0; jj < 6; ++jj) {
                        float2 v = unpk(acc[m][jj]);
                        v.x += bias[jj]; v.y += bias[jj];
                        float2 c = *reinterpret_cast<const float2*>(
                            S2 + (j0 + jj) * NT + tb + 2 * m);
                        float2* sp = reinterpret_cast<float2*>(
                            Ss + (j0 + jj) * SSTR + tb + 2 * m);
                        *sp = make_float2(sigf(v.x) * tanh_f(c.x),
                                          sigf(v.y) * tanh_f(c.y));
                    }
                }
            }
            __syncthreads();  // publish h2 staging
            float* hb = g_h2 + (size_t)b * (NT * NH);
            for (int idx = tid; idx < NT * NH; idx += NTHR) {
                int t = idx / NH, j = idx - t * NH;
                hb[idx] = Ss[j * SSTR + t];
            }
        }
    }
}

// Output GEMM: logits[b,n] partial over K-split. Grid (10 ksplit, 32 b-blocks), 256 thr.
__global__ void __launch_bounds__(256, 1)
out_gemm_kernel(const float* __restrict__ W) {
    extern __shared__ float sm[];
    float* Hs = sm;           // 240*33 = 7920 floats
    float* Wt = sm + 7920;    // 240*44 = 10560 floats

    const int b0 = blockIdx.y * 32;
    const int k0 = blockIdx.x * 2160;
    const int tid = threadIdx.x, wi = tid >> 5, lane = tid & 31;

    float acc[40];
#pragma unroll
    for (int n = 0; n < 40; ++n) acc[n] = 0.f;

    for (int tile = 0; tile < 9; ++tile) {
        const int kt = k0 + tile * 240;
        __syncthreads();
        for (int idx = tid; idx < 32 * 240; idx += 256) {
            int bb = idx / 240, k = idx - bb * 240;
            Hs[k * 33 + bb] = g_h2[(size_t)(b0 + bb) * 21600 + kt + k];
        }
        for (int idx = tid; idx < 40 * 240; idx += 256) {
            int n = idx / 240, k = idx - n * 240;
            Wt[k * 44 + n] = W[(size_t)n * 21600 + kt + k];
        }
        __syncthreads();
#pragma unroll 2
        for (int kk = 0; kk < 30; ++kk) {
            int k = wi * 30 + kk;
            float h = Hs[k * 33 + lane];
            const float4* wp = reinterpret_cast<const float4*>(Wt + k * 44);
#pragma unroll
            for (int n4 = 0; n4 < 10; ++n4) {
                float4 w = wp[n4];
                acc[n4 * 4 + 0] += h * w.x;
                acc[n4 * 4 + 1] += h * w.y;
                acc[n4 * 4 + 2] += h * w.z;
                acc[n4 * 4 + 3] += h * w.w;
            }
        }
    }

    __syncthreads();
    float* Rs = sm;  // reuse: 8*32*40 = 10240 floats
#pragma unroll
    for (int n = 0; n < 40; ++n) Rs[(wi * 32 + lane) * 40 + n] = acc[n];
    __syncthreads();
    for (int idx = tid; idx < 32 * 40; idx += 256) {
        int bb = idx / 40, n = idx - bb * 40;
        float s = 0.f;
#pragma unroll
        for (int w = 0; w < 8; ++w) s += Rs[(w * 32 + bb) * 40 + n];
        g_part[blockIdx.x * (NB * 40) + (b0 + bb) * 40 + n] = s;
    }
}

// Reduce k-splits + bias + grouped softmax (groups of 10). Grid 1024, block 40.
__global__ void softmax_kernel(const float* __restrict__ ob, float* __restrict__ out) {
    __shared__ float L[40];
    __shared__ float E[40];
    const int b = blockIdx.x, n = threadIdx.x;
    float s = 0.f;
#pragma unroll
    for (int ks = 0; ks < 10; ++ks) s += g_part[ks * (NB * 40) + b * 40 + n];
    s += ob[n];
    L[n] = s;
    __syncthreads();
    const int g0 = (n / 10) * 10;
    float mx = -1e30f;
#pragma unroll
    for (int i = 0; i < 10; ++i) mx = fmaxf(mx, L[g0 + i]);
    float e = __expf(s - mx);
    E[n] = e;
    __syncthreads();
    float sum = 0.f;
#pragma unroll
    for (int i = 0; i < 10; ++i) sum += E[g0 + i];
    out[b * 40 + n] = __fdividef(e, sum);
}

extern "C" void kernel_launch(void* const* d_in, const int* in_sizes, int n_in,
                              void* d_out, int out_size) {
    const float* x   = (const float*)d_in[0];
    const float* eW  = (const float*)d_in[1];
    const float* eb1 = (const float*)d_in[2];
    const float* eb2 = (const float*)d_in[3];
    const float* dW  = (const float*)d_in[4];
    const float* db1 = (const float*)d_in[5];
    const float* db2 = (const float*)d_in[6];
    const float* oW  = (const float*)d_in[7];
    const float* ob  = (const float*)d_in[8];
    float* out = (float*)d_out;

    cudaFuncSetAttribute(fused_lstm_kernel,
                         cudaFuncAttributeMaxDynamicSharedMemorySize,
                         SMEM_FLOATS * 4);
    cudaFuncSetAttribute(out_gemm_kernel,
                         cudaFuncAttributeMaxDynamicSharedMemorySize, 73920);

    fused_lstm_kernel<<<NB, NTHR, SMEM_FLOATS * 4>>>(x, eW, eb1, eb2, dW, db1, db2);
    out_gemm_kernel<<<dim3(10, 32), 256, 73920>>>(oW);
    softmax_kernel<<<NB, 40>>>(ob, out);
}

// round 3
// speedup vs baseline: 1.1476x; 1.0030x over previous
#include <cuda_runtime.h>

#define NB 1024
#define NT 240
#define NH 90
#define NF 180
#define SSTR 244          // padded Ss row stride (conflict-aware)
#define NTHR 480

typedef unsigned long long ull;

// scratch (alloc-free rule: __device__ globals)
__device__ float g_h2[(size_t)NB * NT * NH];     // [B][T][H]
__device__ float g_part[10 * NB * 40];           // k-split partial logits

static __device__ __forceinline__ float sigf(float x) {
    return __fdividef(1.f, 1.f + __expf(-x));
}
static __device__ __forceinline__ float tanh_f(float x) {
    float e = __expf(2.f * x);
    return __fdividef(e - 1.f, e + 1.f);
}
static __device__ __forceinline__ void ffma2(ull& c, ull a, ull b) {
    asm("fma.rn.f32x2 %0, %1, %2, %0;" : "+l"(c) : "l"(a), "l"(b));
}
static __device__ __forceinline__ ull pack2(float x, float y) {
    ull r;
    asm("mov.b64 %0, {%1, %2};" : "=l"(r)
        : "r"(__float_as_uint(x)), "r"(__float_as_uint(y)));
    return r;
}
static __device__ __forceinline__ float2 unpk(ull v) {
    unsigned int lo, hi;
    asm("mov.b64 {%0, %1}, %2;" : "=r"(lo), "=r"(hi) : "l"(v));
    return make_float2(__uint_as_float(lo), __uint_as_float(hi));
}

// Per-warp tile: 6 j-cols (warp-uniform, broadcast w) x 8 t per lane (4 f32x2 pairs).
// arow pre-offset by lane (tb floats); wrow pre-offset by j0.
template <int K, int ASTR>
static __device__ __forceinline__ void gemm_block(const float* __restrict__ arow,
                                                  const float* __restrict__ wrow,
                                                  ull acc[4][6]) {
#pragma unroll 6
    for (int k = 0; k < K; ++k) {
        float4 aA = *reinterpret_cast<const float4*>(arow);
        float4 aB = *reinterpret_cast<const float4*>(arow + 4);
        ull a0 = pack2(aA.x, aA.y), a1 = pack2(aA.z, aA.w);
        ull a2 = pack2(aB.x, aB.y), a3 = pack2(aB.z, aB.w);
        float2 w01 = *reinterpret_cast<const float2*>(wrow);
        float2 w23 = *reinterpret_cast<const float2*>(wrow + 2);
        float2 w45 = *reinterpret_cast<const float2*>(wrow + 4);
        float wcol[6] = {w01.x, w01.y, w23.x, w23.y, w45.x, w45.y};
#pragma unroll
        for (int jj = 0; jj < 6; ++jj) {
            ull wv = pack2(wcol[jj], wcol[jj]);
            ffma2(acc[0][jj], a0, wv);
            ffma2(acc[1][jj], a1, wv);
            ffma2(acc[2][jj], a2, wv);
            ffma2(acc[3][jj], a3, wv);
        }
        arow += ASTR;
        wrow += NH;
    }
}

// smem layout (floats):
//  Ss  [0,      21960)  h1 / final h2 staging, 90 x SSTR
//  As  [21960,  36360)  encoder x k-chunk, 60 x 240
//  Ws  [36360,  52560)  encoder W^T chunk-major, 180 x 90
//  S2  [21960,  43560)  decoder i/c staging, 90 x 240 (reuses As+Ws-head)
//  Wd  [44460,  52560)  decoder W^T, 90 x 90 (tail of Ws region)
#define OFF_SS 0
#define OFF_AS 21960
#define OFF_WS 36360
#define OFF_S2 21960
#define OFF_WD 44460
#define SMEM_FLOATS 52560

__global__ void __launch_bounds__(NTHR, 1)
fused_lstm_kernel(const float* __restrict__ x,
                  const float* __restrict__ eW,  const float* __restrict__ eb1,
                  const float* __restrict__ eb2, const float* __restrict__ dW,
                  const float* __restrict__ db1, const float* __restrict__ db2) {
    extern __shared__ float sm[];
    float* Ss = sm + OFF_SS;
    float* As = sm + OFF_AS;
    float* Ws = sm + OFF_WS;
    float* S2 = sm + OFF_S2;
    float* Wd = sm + OFF_WD;

    const int tid  = threadIdx.x;
    const int wid  = tid >> 5;
    const int lane = tid & 31;
    const int b    = blockIdx.x;
    const int j0   = wid * 6;
    const bool act = lane < 30;
    const int tb   = lane * 8;

    const float* xb = x + (size_t)b * (NF * NT);
    const int goff[3] = {0, 180, 270};  // i, g, o rows (f skipped: c0=0)

    // ===== ENCODER (K=180, streamed in 3 chunks of 60) =====
    for (int p = 0; p < 3; ++p) {
        float bias[6];
#pragma unroll
        for (int jj = 0; jj < 6; ++jj)
            bias[jj] = eb1[goff[p] + j0 + jj] + eb2[goff[p] + j0 + jj];

        __syncthreads();  // previous pass's Ws readers done
        {
            const float* wsrc = eW + goff[p] * NF;
            for (int idx = tid; idx < NH * NF; idx += NTHR) {
                int j = idx / NF, k = idx - j * NF;
                Ws[k * NH + j] = wsrc[j * NF + k];
            }
        }

        ull acc[4][6];
#pragma unroll
        for (int m = 0; m < 4; ++m)
#pragma unroll
            for (int jj = 0; jj < 6; ++jj) acc[m][jj] = 0ull;

        for (int kc = 0; kc < 3; ++kc) {
            __syncthreads();  // prior chunk readers done (kc=0: nothing pending)
            const float4* src = reinterpret_cast<const float4*>(xb + kc * 14400);
            float4* dst = reinterpret_cast<float4*>(As);
            for (int i = tid; i < 3600; i += NTHR) dst[i] = src[i];
            __syncthreads();  // publish As chunk (and Ws on kc=0)
            if (act)
                gemm_block<60, NT>(As + tb, Ws + kc * 60 * NH + j0, acc);
        }

        if (act) {
#pragma unroll
            for (int m = 0; m < 4; ++m) {
#pragma unroll
                for (int jj = 0; jj < 6; ++jj) {
                    float2 v = unpk(acc[m][jj]);
                    v.x += bias[jj]; v.y += bias[jj];
                    float2* sp = reinterpret_cast<float2*>(
                        Ss + (j0 + jj) * SSTR + tb + 2 * m);
                    if (p == 0) {                       // i
                        *sp = make_float2(sigf(v.x), sigf(v.y));
                    } else if (p == 1) {                // g -> c = sig(i)*tanh(g)
                        float2 si = *sp;
                        *sp = make_float2(si.x * tanh_f(v.x), si.y * tanh_f(v.y));
                    } else {                            // o -> h1 = sig(sig(o)*tanh(c))
                        float2 c = *sp;
                        *sp = make_float2(sigf(sigf(v.x) * tanh_f(c.x)),
                                          sigf(sigf(v.y) * tanh_f(c.y)));
                    }
                }
            }
        }
    }

    // ===== DECODER (K=90, A = Ss resident) =====
    for (int p = 0; p < 3; ++p) {
        float bias[6];
#pragma unroll
        for (int jj = 0; jj < 6; ++jj)
            bias[jj] = db1[goff[p] + j0 + jj] + db2[goff[p] + j0 + jj];

        __syncthreads();  // prior gemm readers of Wd done; encoder Ss writes done
        {
            const float* wsrc = dW + goff[p] * NH;
            for (int idx = tid; idx < NH * NH; idx += NTHR) {
                int j = idx / NH, k = idx - j * NH;
                Wd[k * NH + j] = wsrc[j * NH + k];
            }
        }
        __syncthreads();  // publish Wd

        ull acc[4][6];
#pragma unroll
        for (int m = 0; m < 4; ++m)
#pragma unroll
            for (int jj = 0; jj < 6; ++jj) acc[m][jj] = 0ull;

        if (act) gemm_block<90, SSTR>(Ss + tb, Wd + j0, acc);

        if (p < 2) {
            if (act) {
#pragma unroll
                for (int m = 0; m < 4; ++m) {
#pragma unroll
                    for (int jj = 0; jj < 6; ++jj) {
                        float2 v = unpk(acc[m][jj]);
                        v.x += bias[jj]; v.y += bias[jj];
                        float2* sp = reinterpret_cast<float2*>(
                            S2 + (j0 + jj) * NT + tb + 2 * m);
                        if (p == 0) {
                            *sp = make_float2(sigf(v.x), sigf(v.y));
                        } else {
                            float2 si = *sp;
                            *sp = make_float2(si.x * tanh_f(v.x),
                                              si.y * tanh_f(v.y));
                        }
                    }
                }
            }
        } else {
            __syncthreads();  // all gemm reads of Ss complete before overwrite
            if (act) {
#pragma unroll
                for (int m = 0; m < 4; ++m) {
#pragma unroll
                    for (int jj = 0; jj < 6; ++jj) {
                        float2 v = unpk(acc[m][jj]);
                        v.x += bias[jj]; v.y += bias[jj];
                        float2 c = *reinterpret_cast<const float2*>(
                            S2 + (j0 + jj) * NT + tb + 2 * m);
                        float2* sp = reinterpret_cast<float2*>(
                            Ss + (j0 + jj) * SSTR + tb + 2 * m);
                        *sp = make_float2(sigf(v.x) * tanh_f(c.x),
                                          sigf(v.y) * tanh_f(c.y));
                    }
                }
            }
            __syncthreads();  // publish h2 staging
            float* hb = g_h2 + (size_t)b * (NT * NH);
            for (int idx = tid; idx < NT * NH; idx += NTHR) {
                int t = idx / NH, j = idx - t * NH;
                hb[idx] = Ss[j * SSTR + t];
            }
        }
    }
}

// Output GEMM: logits[b,n] partial over K-split. Grid (10 ksplit, 32 b-blocks), 256 thr.
__global__ void __launch_bounds__(256, 1)
out_gemm_kernel(const float* __restrict__ W) {
    extern __shared__ float sm[];
    float* Hs = sm;           // 240*33 = 7920 floats
    float* Wt = sm + 7920;    // 240*44 = 10560 floats

    const int b0 = blockIdx.y * 32;
    const int k0 = blockIdx.x * 2160;
    const int tid = threadIdx.x, wi = tid >> 5, lane = tid & 31;

    float acc[40];
#pragma unroll
    for (int n = 0; n < 40; ++n) acc[n] = 0.f;

    for (int tile = 0; tile < 9; ++tile) {
        const int kt = k0 + tile * 240;
        __syncthreads();
        for (int idx = tid; idx < 32 * 240; idx += 256) {
            int bb = idx / 240, k = idx - bb * 240;
            Hs[k * 33 + bb] = g_h2[(size_t)(b0 + bb) * 21600 + kt + k];
        }
        for (int idx = tid; idx < 40 * 240; idx += 256) {
            int n = idx / 240, k = idx - n * 240;
            Wt[k * 44 + n] = W[(size_t)n * 21600 + kt + k];
        }
        __syncthreads();
#pragma unroll 2
        for (int kk = 0; kk < 30; ++kk) {
            int k = wi * 30 + kk;
            float h = Hs[k * 33 + lane];
            const float4* wp = reinterpret_cast<const float4*>(Wt + k * 44);
#pragma unroll
            for (int n4 = 0; n4 < 10; ++n4) {
                float4 w = wp[n4];
                acc[n4 * 4 + 0] += h * w.x;
                acc[n4 * 4 + 1] += h * w.y;
                acc[n4 * 4 + 2] += h * w.z;
                acc[n4 * 4 + 3] += h * w.w;
            }
        }
    }

    __syncthreads();
    float* Rs = sm;  // reuse: 8*32*40 = 10240 floats
#pragma unroll
    for (int n = 0; n < 40; ++n) Rs[(wi * 32 + lane) * 40 + n] = acc[n];
    __syncthreads();
    for (int idx = tid; idx < 32 * 40; idx += 256) {
        int bb = idx / 40, n = idx - bb * 40;
        float s = 0.f;
#pragma unroll
        for (int w = 0; w < 8; ++w) s += Rs[(w * 32 + bb) * 40 + n];
        g_part[blockIdx.x * (NB * 40) + (b0 + bb) * 40 + n] = s;
    }
}

// Reduce k-splits + bias + grouped softmax (groups of 10). Grid 1024, block 40.
__global__ void softmax_kernel(const float* __restrict__ ob, float* __restrict__ out) {
    __shared__ float L[40];
    __shared__ float E[40];
    const int b = blockIdx.x, n = threadIdx.x;
    float s = 0.f;
#pragma unroll
    for (int ks = 0; ks < 10; ++ks) s += g_part[ks * (NB * 40) + b * 40 + n];
    s += ob[n];
    L[n] = s;
    __syncthreads();
    const int g0 = (n / 10) * 10;
    float mx = -1e30f;
#pragma unroll
    for (int i = 0; i < 10; ++i) mx = fmaxf(mx, L[g0 + i]);
    float e = __expf(s - mx);
    E[n] = e;
    __syncthreads();
    float sum = 0.f;
#pragma unroll
    for (int i = 0; i < 10; ++i) sum += E[g0 + i];
    out[b * 40 + n] = __fdividef(e, sum);
}

extern "C" void kernel_launch(void* const* d_in, const int* in_sizes, int n_in,
                              void* d_out, int out_size) {
    const float* x   = (const float*)d_in[0];
    const float* eW  = (const float*)d_in[1];
    const float* eb1 = (const float*)d_in[2];
    const float* eb2 = (const float*)d_in[3];
    const float* dW  = (const float*)d_in[4];
    const float* db1 = (const float*)d_in[5];
    const float* db2 = (const float*)d_in[6];
    const float* oW  = (const float*)d_in[7];
    const float* ob  = (const float*)d_in[8];
    float* out = (float*)d_out;

    cudaFuncSetAttribute(fused_lstm_kernel,
                         cudaFuncAttributeMaxDynamicSharedMemorySize,
                         SMEM_FLOATS * 4);
    cudaFuncSetAttribute(out_gemm_kernel,
                         cudaFuncAttributeMaxDynamicSharedMemorySize, 73920);

    fused_lstm_kernel<<<NB, NTHR, SMEM_FLOATS * 4>>>(x, eW, eb1, eb2, dW, db1, db2);
    out_gemm_kernel<<<dim3(10, 32), 256, 73920>>>(oW);
    softmax_kernel<<<NB, 40>>>(ob, out);
}

// round 5
// speedup vs baseline: 1.5721x; 1.3699x over previous
#include <cuda_runtime.h>
#include <cuda_bf16.h>
#include <cstdint>

#define NB 1024
#define NT 240
#define NH 90
#define NF 180
#define KS 30            // output-gemm k-splits

// ---- frag-image sizes (u32 words) ----
#define EB_G (12*32*28)  // 10752 words per enc gate per image
#define DB_G (6*32*28)   // 5376  words per dec gate per image

// ---- lstm smem byte offsets ----
#define OFF_AH 0                 // enc Ah [12][8][32][4]u32 = 49152
#define OFF_AL 49152             // enc Al
#define OFF_ADH 0                // dec Ah [6][8][32][4]u32 = 24576 (reuse)
#define OFF_ADL 24576            // dec Al
#define OFF_B  98304             // Bh (43008) then Bl (43008)
#define OFF_BL (OFF_B + 43008)
#define SMEM_LSTM (OFF_B + 2*43008)   // 184320

__device__ __align__(16) uint32_t g_eBFh[3*EB_G], g_eBFl[3*EB_G];
__device__ __align__(16) uint32_t g_dBFh[3*DB_G], g_dBFl[3*DB_G];
__device__ float g_h2[(size_t)NB*NT*NH];
__device__ float g_part[KS*NB*40];

// ---- helpers ----
static __device__ __forceinline__ uint32_t smem_u32(const void* p) {
    uint32_t a;
    asm("{ .reg .u64 t; cvta.to.shared.u64 t, %1; cvt.u32.u64 %0, t; }" : "=r"(a) : "l"(p));
    return a;
}
static __device__ __forceinline__ uint4 lds128(uint32_t a) {
    uint4 v;
    asm volatile("ld.shared.v4.b32 {%0,%1,%2,%3}, [%4];"
                 : "=r"(v.x), "=r"(v.y), "=r"(v.z), "=r"(v.w) : "r"(a));
    return v;
}
static __device__ __forceinline__ void sts32(uint32_t a, uint32_t v) {
    asm volatile("st.shared.b32 [%0], %1;" :: "r"(a), "r"(v));
}
static __device__ __forceinline__ void sts64(uint32_t a, uint32_t v0, uint32_t v1) {
    asm volatile("st.shared.v2.b32 [%0], {%1,%2};" :: "r"(a), "r"(v0), "r"(v1));
}
static __device__ __forceinline__ void sts128z(uint32_t a) {
    asm volatile("st.shared.v4.b32 [%0], {%1,%1,%1,%1};" :: "r"(a), "r"(0u));
}
static __device__ __forceinline__ void mma4(float* c, const uint4& a, uint32_t b0, uint32_t b1) {
    asm volatile(
        "mma.sync.aligned.m16n8k16.row.col.f32.bf16.bf16.f32 "
        "{%0,%1,%2,%3}, {%4,%5,%6,%7}, {%8,%9}, {%0,%1,%2,%3};"
        : "+f"(c[0]), "+f"(c[1]), "+f"(c[2]), "+f"(c[3])
        : "r"(a.x), "r"(a.y), "r"(a.z), "r"(a.w), "r"(b0), "r"(b1));
}
static __device__ __forceinline__ float sigf(float x) {
    return __fdividef(1.f, 1.f + __expf(-x));
}
static __device__ __forceinline__ float tanh_f(float x) {
    float e = __expf(2.f * x);
    return __fdividef(e - 1.f, e + 1.f);
}
static __device__ __forceinline__ void packsplit2(float v0, float v1, uint32_t& hi, uint32_t& lo) {
    __nv_bfloat16 h0 = __float2bfloat16(v0), h1 = __float2bfloat16(v1);
    hi = (uint32_t)__bfloat16_as_ushort(h0) | ((uint32_t)__bfloat16_as_ushort(h1) << 16);
    __nv_bfloat16 l0 = __float2bfloat16(v0 - __bfloat162float(h0));
    __nv_bfloat16 l1 = __float2bfloat16(v1 - __bfloat162float(h1));
    lo = (uint32_t)__bfloat16_as_ushort(l0) | ((uint32_t)__bfloat16_as_ushort(l1) << 16);
}

// one warp-tile GEMM pass: A frags [kt][8 mtiles][32 lanes][16B], B frags [kt][32 lanes][28 words]
template <int KT>
static __device__ __forceinline__ void gemm_pass(uint32_t abase, uint32_t bbase,
                                                 int wid, int lane, float* acc) {
#pragma unroll
    for (int kt = 0; kt < KT; ++kt) {
        uint4 a = lds128(abase + (uint32_t)(((kt * 8 + wid) * 32 + lane) * 16));
        uint32_t bl = bbase + (uint32_t)((kt * 32 + lane) * 112);
        uint4 b0 = lds128(bl), b1 = lds128(bl + 16), b2 = lds128(bl + 32);
        uint4 b3 = lds128(bl + 48), b4 = lds128(bl + 64), b5 = lds128(bl + 80);
        mma4(acc + 0,  a, b0.x, b0.y);  mma4(acc + 4,  a, b0.z, b0.w);
        mma4(acc + 8,  a, b1.x, b1.y);  mma4(acc + 12, a, b1.z, b1.w);
        mma4(acc + 16, a, b2.x, b2.y);  mma4(acc + 20, a, b2.z, b2.w);
        mma4(acc + 24, a, b3.x, b3.y);  mma4(acc + 28, a, b3.z, b3.w);
        mma4(acc + 32, a, b4.x, b4.y);  mma4(acc + 36, a, b4.z, b4.w);
        mma4(acc + 40, a, b5.x, b5.y);  mma4(acc + 44, a, b5.z, b5.w);
    }
}

// ===== prep: pack weights (hi/lo split, bias col folded) into frag-major images =====
__global__ void prep_kernel(const float* __restrict__ eW, const float* __restrict__ eb1,
                            const float* __restrict__ eb2, const float* __restrict__ dW,
                            const float* __restrict__ db1, const float* __restrict__ db2) {
    int idx = blockIdx.x * 256 + threadIdx.x;
    const int goff[3] = {0, 180, 270};  // i, g, o (f gate skipped: c0 = 0)
    if (idx < 3 * 96 * 96) {            // encoder: gate x n x kp
        int gate = idx / (96 * 96), rem = idx % (96 * 96);
        int n = rem / 96, kp = rem % 96;
        int k = 2 * kp;
        float v0 = 0.f, v1 = 0.f;
        if (n < NH) {
            if (k < NF) { v0 = eW[(goff[gate] + n) * NF + k]; v1 = eW[(goff[gate] + n) * NF + k + 1]; }
            else if (k == NF) v0 = eb1[goff[gate] + n] + eb2[goff[gate] + n];
        }
        uint32_t hi, lo; packsplit2(v0, v1, hi, lo);
        int pos = ((kp >> 3) * 32 + ((n & 7) << 2) + (kp & 3)) * 28 + (n >> 3) * 2 + ((kp >> 2) & 1);
        g_eBFh[gate * EB_G + pos] = hi;
        g_eBFl[gate * EB_G + pos] = lo;
        return;
    }
    int j = idx - 3 * 96 * 96;
    if (j < 3 * 96 * 48) {              // decoder
        int gate = j / (96 * 48), rem = j % (96 * 48);
        int n = rem / 48, kp = rem % 48;
        int k = 2 * kp;
        float v0 = 0.f, v1 = 0.f;
        if (n < NH) {
            if (k < NH) { v0 = dW[(goff[gate] + n) * NH + k]; v1 = dW[(goff[gate] + n) * NH + k + 1]; }
            else if (k == NH) v0 = db1[goff[gate] + n] + db2[goff[gate] + n];
        }
        uint32_t hi, lo; packsplit2(v0, v1, hi, lo);
        int pos = ((kp >> 3) * 32 + ((n & 7) << 2) + (kp & 3)) * 28 + (n >> 3) * 2 + ((kp >> 2) & 1);
        g_dBFh[gate * DB_G + pos] = hi;
        g_dBFl[gate * DB_G + pos] = lo;
    }
}

// ===== fused LSTM on mma.sync =====
__global__ void __launch_bounds__(256, 1)
lstm_mma_kernel(const float* __restrict__ x) {
    extern __shared__ char smem[];
    const uint32_t sb = smem_u32(smem);
    const int tid = threadIdx.x, wid = tid >> 5, lane = tid & 31;
    const int b = blockIdx.x >> 1, th = blockIdx.x & 1;
    const int t0 = th * 120;
    const int tig = lane & 3, q = lane >> 2;

    // zero enc A region (hi+lo = 98304B)
    for (int i = tid; i < 6144; i += 256) sts128z(sb + (uint32_t)(i * 16));

    // stage x (coalesced) then scatter split into A frags; two 90-feature phases
    float* Sx = reinterpret_cast<float*>(smem + OFF_B);
    for (int ph = 0; ph < 2; ++ph) {
        __syncthreads();
        const float* xb = x + ((size_t)b * NF + ph * 90) * NT + t0;
        for (int i = tid; i < 2700; i += 256) {
            int f = i / 30, c = i % 30;
            const float4 v = *reinterpret_cast<const float4*>(xb + f * NT + c * 4);
            *reinterpret_cast<float4*>(Sx + f * 120 + c * 4) = v;
        }
        __syncthreads();
        for (int i = tid; i < 5400; i += 256) {
            int r = i / 45, kpl = i % 45;
            int kp = ph * 45 + kpl, fp = 2 * kpl;
            float v0 = Sx[fp * 120 + r], v1 = Sx[(fp + 1) * 120 + r];
            uint32_t hi, lo; packsplit2(v0, v1, hi, lo);
            int rr = r & 15, mt = r >> 4;
            int lne = ((rr & 7) << 2) | (kp & 3);
            int reg = (((kp >> 2) & 1) << 1) | (rr >> 3);
            uint32_t woff = (uint32_t)(((((kp >> 3) * 8 + mt) * 32 + lne) * 4 + reg) * 4);
            sts32(sb + OFF_AH + woff, hi);
            sts32(sb + OFF_AL + woff, lo);
        }
    }
    // enc bias column (k=180 -> ktile 11, lane k-part 2, regs 0&1), Ah=1.0, Al stays 0
    if (tid < 64) {
        int mt = tid >> 3, qq = tid & 7;
        uint32_t addr = sb + OFF_AH + (uint32_t)((((11 * 8 + mt) * 32 + ((qq << 2) | 2)) * 4) * 4);
        sts64(addr, 0x00003F80u, 0x00003F80u);
    }

    float acc[48], sv[48];

    // ===== encoder: 3 gates =====
    for (int gate = 0; gate < 3; ++gate) {
        __syncthreads();  // Sx / previous gate's B readers done
        {
            const uint4* sh = reinterpret_cast<const uint4*>(g_eBFh + gate * EB_G);
            const uint4* sl = reinterpret_cast<const uint4*>(g_eBFl + gate * EB_G);
            uint4* dh = reinterpret_cast<uint4*>(smem + OFF_B);
            uint4* dl = reinterpret_cast<uint4*>(smem + OFF_BL);
            for (int i = tid; i < 2688; i += 256) { dh[i] = sh[i]; dl[i] = sl[i]; }
        }
        __syncthreads();

#pragma unroll
        for (int i = 0; i < 48; ++i) acc[i] = 0.f;
        gemm_pass<12>(sb + OFF_AH, sb + OFF_B,  wid, lane, acc);
        gemm_pass<12>(sb + OFF_AH, sb + OFF_BL, wid, lane, acc);
        gemm_pass<12>(sb + OFF_AL, sb + OFF_B,  wid, lane, acc);

        if (gate == 0) {
#pragma unroll
            for (int i = 0; i < 48; ++i) sv[i] = sigf(acc[i]);
        } else if (gate == 1) {
#pragma unroll
            for (int i = 0; i < 48; ++i) sv[i] = sv[i] * tanh_f(acc[i]);   // c
        } else {
            // h1 = sig(sig(o) * tanh(c)); split into decoder A frags (own-lane writes)
#pragma unroll
            for (int nt = 0; nt < 12; ++nt) {
                float h0 = sigf(sigf(acc[nt * 4 + 0]) * tanh_f(sv[nt * 4 + 0]));
                float h1 = sigf(sigf(acc[nt * 4 + 1]) * tanh_f(sv[nt * 4 + 1]));
                float h2 = sigf(sigf(acc[nt * 4 + 2]) * tanh_f(sv[nt * 4 + 2]));
                float h3 = sigf(sigf(acc[nt * 4 + 3]) * tanh_f(sv[nt * 4 + 3]));
                uint32_t hiA, loA, hiB, loB;
                if (nt == 11 && tig >= 1) {
                    hiA = hiB = (tig == 1) ? 0x00003F80u : 0u;   // dec bias col j=90 / zero pad
                    loA = loB = 0u;
                } else {
                    packsplit2(h0, h1, hiA, loA);
                    packsplit2(h2, h3, hiB, loB);
                }
                uint32_t roff = (uint32_t)(((((nt >> 1) * 8 + wid) * 32 + lane) * 16) + ((nt & 1) << 3));
                sts64(sb + OFF_ADH + roff, hiA, hiB);
                sts64(sb + OFF_ADL + roff, loA, loB);
            }
        }
    }

    // ===== decoder: 3 gates =====
    for (int gate = 0; gate < 3; ++gate) {
        __syncthreads();
        {
            const uint4* sh = reinterpret_cast<const uint4*>(g_dBFh + gate * DB_G);
            const uint4* sl = reinterpret_cast<const uint4*>(g_dBFl + gate * DB_G);
            uint4* dh = reinterpret_cast<uint4*>(smem + OFF_B);
            uint4* dl = reinterpret_cast<uint4*>(smem + OFF_BL);
            for (int i = tid; i < 1344; i += 256) { dh[i] = sh[i]; dl[i] = sl[i]; }
        }
        __syncthreads();

#pragma unroll
        for (int i = 0; i < 48; ++i) acc[i] = 0.f;
        gemm_pass<6>(sb + OFF_ADH, sb + OFF_B,  wid, lane, acc);
        gemm_pass<6>(sb + OFF_ADH, sb + OFF_BL, wid, lane, acc);
        gemm_pass<6>(sb + OFF_ADL, sb + OFF_B,  wid, lane, acc);

        if (gate == 0) {
#pragma unroll
            for (int i = 0; i < 48; ++i) sv[i] = sigf(acc[i]);
        } else if (gate == 1) {
#pragma unroll
            for (int i = 0; i < 48; ++i) sv[i] = sv[i] * tanh_f(acc[i]);   // c
        } else {
            // h2 = sig(o) * tanh(c) -> g_h2[b][t0+t][j]
            float* hb = g_h2 + (size_t)b * (NT * NH) + (size_t)t0 * NH;
            int r0 = wid * 16 + q;
#pragma unroll
            for (int nt = 0; nt < 12; ++nt) {
                int j = nt * 8 + tig * 2;
                if (j >= NH) continue;   // only nt==11, tig>=1
                float v0 = sigf(acc[nt * 4 + 0]) * tanh_f(sv[nt * 4 + 0]);
                float v1 = sigf(acc[nt * 4 + 1]) * tanh_f(sv[nt * 4 + 1]);
                *reinterpret_cast<float2*>(hb + r0 * NH + j) = make_float2(v0, v1);
                if (wid < 7) {
                    float v2 = sigf(acc[nt * 4 + 2]) * tanh_f(sv[nt * 4 + 2]);
                    float v3 = sigf(acc[nt * 4 + 3]) * tanh_f(sv[nt * 4 + 3]);
                    *reinterpret_cast<float2*>(hb + (r0 + 8) * NH + j) = make_float2(v2, v3);
                }
            }
        }
    }
}

// ===== output GEMM (k-split partials) =====
__global__ void __launch_bounds__(256, 1)
out_gemm_kernel(const float* __restrict__ W) {
    extern __shared__ float sm[];
    float* Hs = sm;           // 240*33
    float* Wt = sm + 7920;    // 240*44
    const int b0 = blockIdx.y * 32;
    const int k0 = blockIdx.x * (21600 / KS);
    const int tid = threadIdx.x, wi = tid >> 5, lane = tid & 31;

    float acc[40];
#pragma unroll
    for (int n = 0; n < 40; ++n) acc[n] = 0.f;

    for (int tile = 0; tile < (21600 / KS) / 240; ++tile) {
        const int kt = k0 + tile * 240;
        __syncthreads();
        for (int idx = tid; idx < 32 * 240; idx += 256) {
            int bb = idx / 240, k = idx - bb * 240;
            Hs[k * 33 + bb] = g_h2[(size_t)(b0 + bb) * 21600 + kt + k];
        }
        for (int idx = tid; idx < 40 * 240; idx += 256) {
            int n = idx / 240, k = idx - n * 240;
            Wt[k * 44 + n] = W[(size_t)n * 21600 + kt + k];
        }
        __syncthreads();
#pragma unroll 2
        for (int kk = 0; kk < 30; ++kk) {
            int k = wi * 30 + kk;
            float h = Hs[k * 33 + lane];
            const float4* wp = reinterpret_cast<const float4*>(Wt + k * 44);
#pragma unroll
            for (int n4 = 0; n4 < 10; ++n4) {
                float4 w = wp[n4];
                acc[n4 * 4 + 0] += h * w.x;
                acc[n4 * 4 + 1] += h * w.y;
                acc[n4 * 4 + 2] += h * w.z;
                acc[n4 * 4 + 3] += h * w.w;
            }
        }
    }
    __syncthreads();
    float* Rs = sm;
#pragma unroll
    for (int n = 0; n < 40; ++n) Rs[(wi * 32 + lane) * 40 + n] = acc[n];
    __syncthreads();
    for (int idx = tid; idx < 32 * 40; idx += 256) {
        int bb = idx / 40, n = idx - bb * 40;
        float s = 0.f;
#pragma unroll
        for (int w = 0; w < 8; ++w) s += Rs[(w * 32 + bb) * 40 + n];
        g_part[blockIdx.x * (NB * 40) + (b0 + bb) * 40 + n] = s;
    }
}

__global__ void softmax_kernel(const float* __restrict__ ob, float* __restrict__ out) {
    __shared__ float L[40];
    __shared__ float E[40];
    const int b = blockIdx.x, n = threadIdx.x;
    float s = 0.f;
#pragma unroll
    for (int ks = 0; ks < KS; ++ks) s += g_part[ks * (NB * 40) + b * 40 + n];
    s += ob[n];
    L[n] = s;
    __syncthreads();
    const int g0 = (n / 10) * 10;
    float mx = -1e30f;
#pragma unroll
    for (int i = 0; i < 10; ++i) mx = fmaxf(mx, L[g0 + i]);
    float e = __expf(s - mx);
    E[n] = e;
    __syncthreads();
    float sum = 0.f;
#pragma unroll
    for (int i = 0; i < 10; ++i) sum += E[g0 + i];
    out[b * 40 + n] = __fdividef(e, sum);
}

extern "C" void kernel_launch(void* const* d_in, const int* in_sizes, int n_in,
                              void* d_out, int out_size) {
    const float* x   = (const float*)d_in[0];
    const float* eW  = (const float*)d_in[1];
    const float* eb1 = (const float*)d_in[2];
    const float* eb2 = (const float*)d_in[3];
    const float* dW  = (const float*)d_in[4];
    const float* db1 = (const float*)d_in[5];
    const float* db2 = (const float*)d_in[6];
    const float* oW  = (const float*)d_in[7];
    const float* ob  = (const float*)d_in[8];
    float* out = (float*)d_out;

    cudaFuncSetAttribute(lstm_mma_kernel,
                         cudaFuncAttributeMaxDynamicSharedMemorySize, SMEM_LSTM);
    cudaFuncSetAttribute(out_gemm_kernel,
                         cudaFuncAttributeMaxDynamicSharedMemorySize, 73920);

    prep_kernel<<<162, 256>>>(eW, eb1, eb2, dW, db1, db2);
    lstm_mma_kernel<<<2048, 256, SMEM_LSTM>>>(x);
    out_gemm_kernel<<<dim3(KS, 32), 256, 73920>>>(oW);
    softmax_kernel<<<NB, 40>>>(ob, out);
}

// round 6
// speedup vs baseline: 2.3843x; 1.5166x over previous
#include <cuda_runtime.h>
#include <cuda_bf16.h>
#include <cstdint>

#define NB 1024
#define NT 240
#define NH 90
#define NF 180
#define KS 30

// frag-image sizes (u32 words)
#define EB_G (12*32*28)  // enc gate image
#define DB_G (6*32*28)   // dec gate image

// lstm smem layout (bytes)
#define OFF_AH  0        // enc A hi [12kt][8mt][32][16B] = 49152
#define OFF_AL  49152    // enc A lo
#define OFF_ADH 0        // dec A hi [6kt][8][32][16B] = 24576 (reuse)
#define OFF_ADL 24576    // dec A lo
#define OFF_B   98304    // 2 x 43008 chunk buffers (hi 21504 | lo 21504 each)
#define CHUNK_B 43008
#define SMEM_LSTM (OFF_B + 2*CHUNK_B)   // 184320

__device__ __align__(16) uint32_t g_eBFh[3*EB_G], g_eBFl[3*EB_G];
__device__ __align__(16) uint32_t g_dBFh[3*DB_G], g_dBFl[3*DB_G];
__device__ float g_h2[(size_t)NB*NT*NH];
__device__ float g_part[KS*NB*40];

// ---- helpers ----
static __device__ __forceinline__ uint32_t smem_u32(const void* p) {
    uint32_t a;
    asm("{ .reg .u64 t; cvta.to.shared.u64 t, %1; cvt.u32.u64 %0, t; }" : "=r"(a) : "l"(p));
    return a;
}
static __device__ __forceinline__ uint4 lds128(uint32_t a) {
    uint4 v;
    asm volatile("ld.shared.v4.b32 {%0,%1,%2,%3}, [%4];"
                 : "=r"(v.x), "=r"(v.y), "=r"(v.z), "=r"(v.w) : "r"(a));
    return v;
}
static __device__ __forceinline__ void sts32(uint32_t a, uint32_t v) {
    asm volatile("st.shared.b32 [%0], %1;" :: "r"(a), "r"(v));
}
static __device__ __forceinline__ void sts64(uint32_t a, uint32_t v0, uint32_t v1) {
    asm volatile("st.shared.v2.b32 [%0], {%1,%2};" :: "r"(a), "r"(v0), "r"(v1));
}
static __device__ __forceinline__ void sts128z(uint32_t a) {
    asm volatile("st.shared.v4.b32 [%0], {%1,%1,%1,%1};" :: "r"(a), "r"(0u));
}
static __device__ __forceinline__ void cp16(uint32_t saddr, const void* g) {
    asm volatile("{ .reg .u64 gp; cvta.to.global.u64 gp, %1;"
                 "  cp.async.cg.shared.global [%0], [gp], 16; }"
                 :: "r"(saddr), "l"(g) : "memory");
}
#define CP_COMMIT() asm volatile("cp.async.commit_group;" ::: "memory")
#define CP_WAIT1()  asm volatile("cp.async.wait_group 1;" ::: "memory")
#define CP_WAIT0()  asm volatile("cp.async.wait_group 0;" ::: "memory")

static __device__ __forceinline__ void mma4(float* c, const uint4& a, uint32_t b0, uint32_t b1) {
    asm volatile(
        "mma.sync.aligned.m16n8k16.row.col.f32.bf16.bf16.f32 "
        "{%0,%1,%2,%3}, {%4,%5,%6,%7}, {%8,%9}, {%0,%1,%2,%3};"
        : "+f"(c[0]), "+f"(c[1]), "+f"(c[2]), "+f"(c[3])
        : "r"(a.x), "r"(a.y), "r"(a.z), "r"(a.w), "r"(b0), "r"(b1));
}
static __device__ __forceinline__ float tanhA(float x) {
    float y;
    asm("tanh.approx.f32 %0, %1;" : "=f"(y) : "f"(x));
    return y;
}
static __device__ __forceinline__ float sigA(float x) {
    return fmaf(tanhA(0.5f * x), 0.5f, 0.5f);
}
static __device__ __forceinline__ void packsplit2(float v0, float v1, uint32_t& hi, uint32_t& lo) {
    __nv_bfloat16 h0 = __float2bfloat16(v0), h1 = __float2bfloat16(v1);
    hi = (uint32_t)__bfloat16_as_ushort(h0) | ((uint32_t)__bfloat16_as_ushort(h1) << 16);
    __nv_bfloat16 l0 = __float2bfloat16(v0 - __bfloat162float(h0));
    __nv_bfloat16 l1 = __float2bfloat16(v1 - __bfloat162float(h1));
    lo = (uint32_t)__bfloat16_as_ushort(l0) | ((uint32_t)__bfloat16_as_ushort(l1) << 16);
}

#define MMA6(accp, A, B0, B1, B2) \
    mma4((accp) + 0,  A, B0.x, B0.y); mma4((accp) + 4,  A, B0.z, B0.w); \
    mma4((accp) + 8,  A, B1.x, B1.y); mma4((accp) + 12, A, B1.z, B1.w); \
    mma4((accp) + 16, A, B2.x, B2.y); mma4((accp) + 20, A, B2.z, B2.w);

// one 6-kt chunk: split-3 (AhBh + AhBl + AlBh), warp covers 2 mtiles x 6 ntiles
static __device__ __forceinline__ void chunk_mma(uint32_t abH, uint32_t abL,
                                                 uint32_t bbH, uint32_t bbL,
                                                 uint32_t aoffb, uint32_t boffb,
                                                 float* acc) {
#pragma unroll
    for (int kt = 0; kt < 6; ++kt) {
        uint32_t aa = abH + kt * 4096 + aoffb;
        uint4 h0 = lds128(aa), h1 = lds128(aa + 512);
        uint32_t la = abL + kt * 4096 + aoffb;
        uint4 l0 = lds128(la), l1 = lds128(la + 512);
        uint32_t bo = kt * 3584 + boffb;
        uint4 B0 = lds128(bbH + bo), B1 = lds128(bbH + bo + 16), B2 = lds128(bbH + bo + 32);
        uint4 C0 = lds128(bbL + bo), C1 = lds128(bbL + bo + 16), C2 = lds128(bbL + bo + 32);
        MMA6(acc,      h0, B0, B1, B2);
        MMA6(acc + 24, h1, B0, B1, B2);
        MMA6(acc,      h0, C0, C1, C2);
        MMA6(acc + 24, h1, C0, C1, C2);
        MMA6(acc,      l0, B0, B1, B2);
        MMA6(acc + 24, l1, B0, B1, B2);
    }
}

// ===== prep: pack weights (hi/lo split, bias folded) into frag-major images =====
__global__ void prep_kernel(const float* __restrict__ eW, const float* __restrict__ eb1,
                            const float* __restrict__ eb2, const float* __restrict__ dW,
                            const float* __restrict__ db1, const float* __restrict__ db2) {
    int idx = blockIdx.x * 256 + threadIdx.x;
    const int goff[3] = {0, 180, 270};  // i, g, o (f gate skipped: c0 = 0)
    if (idx < 3 * 96 * 96) {
        int gate = idx / (96 * 96), rem = idx % (96 * 96);
        int n = rem / 96, kp = rem % 96;
        int k = 2 * kp;
        float v0 = 0.f, v1 = 0.f;
        if (n < NH) {
            if (k < NF) { v0 = eW[(goff[gate] + n) * NF + k]; v1 = eW[(goff[gate] + n) * NF + k + 1]; }
            else if (k == NF) v0 = eb1[goff[gate] + n] + eb2[goff[gate] + n];
        }
        uint32_t hi, lo; packsplit2(v0, v1, hi, lo);
        int pos = ((kp >> 3) * 32 + ((n & 7) << 2) + (kp & 3)) * 28 + (n >> 3) * 2 + ((kp >> 2) & 1);
        g_eBFh[gate * EB_G + pos] = hi;
        g_eBFl[gate * EB_G + pos] = lo;
        return;
    }
    int j = idx - 3 * 96 * 96;
    if (j < 3 * 96 * 48) {
        int gate = j / (96 * 48), rem = j % (96 * 48);
        int n = rem / 48, kp = rem % 48;
        int k = 2 * kp;
        float v0 = 0.f, v1 = 0.f;
        if (n < NH) {
            if (k < NH) { v0 = dW[(goff[gate] + n) * NH + k]; v1 = dW[(goff[gate] + n) * NH + k + 1]; }
            else if (k == NH) v0 = db1[goff[gate] + n] + db2[goff[gate] + n];
        }
        uint32_t hi, lo; packsplit2(v0, v1, hi, lo);
        int pos = ((kp >> 3) * 32 + ((n & 7) << 2) + (kp & 3)) * 28 + (n >> 3) * 2 + ((kp >> 2) & 1);
        g_dBFh[gate * DB_G + pos] = hi;
        g_dBFl[gate * DB_G + pos] = lo;
    }
}

// ===== fused LSTM: mma.sync + cp.async pipelined B chunks =====
__global__ void __launch_bounds__(256, 1)
lstm_mma_kernel(const float* __restrict__ x) {
    extern __shared__ char smem[];
    const uint32_t sb = smem_u32(smem);
    const int tid = threadIdx.x, wid = tid >> 5, lane = tid & 31;
    const int b = blockIdx.x >> 1, th = blockIdx.x & 1;
    const int t0 = th * 120;
    const int tig = lane & 3, q = lane >> 2;
    const int mg = wid >> 1, ng = wid & 1;
    const uint32_t aoffb = (uint32_t)(mg * 2 * 512 + lane * 16);
    const uint32_t boffb = (uint32_t)(lane * 112 + ng * 48);

    // zero enc A region (hi+lo = 98304B)
    for (int i = tid; i < 6144; i += 256) sts128z(sb + (uint32_t)(i * 16));

    // stage x coalesced, scatter split into enc A frags (two 90-feature phases)
    float* Sx = reinterpret_cast<float*>(smem + OFF_B);
    for (int ph = 0; ph < 2; ++ph) {
        __syncthreads();
        const float* xb = x + ((size_t)b * NF + ph * 90) * NT + t0;
        for (int i = tid; i < 2700; i += 256) {
            int f = i / 30, c = i % 30;
            const float4 v = *reinterpret_cast<const float4*>(xb + f * NT + c * 4);
            *reinterpret_cast<float4*>(Sx + f * 120 + c * 4) = v;
        }
        __syncthreads();
        for (int i = tid; i < 5400; i += 256) {
            int r = i / 45, kpl = i % 45;
            int kp = ph * 45 + kpl, fp = 2 * kpl;
            float v0 = Sx[fp * 120 + r], v1 = Sx[(fp + 1) * 120 + r];
            uint32_t hi, lo; packsplit2(v0, v1, hi, lo);
            int rr = r & 15, mt = r >> 4;
            int lne = ((rr & 7) << 2) | (kp & 3);
            int reg = (((kp >> 2) & 1) << 1) | (rr >> 3);
            uint32_t woff = (uint32_t)(((((kp >> 3) * 8 + mt) * 32 + lne) * 4 + reg) * 4);
            sts32(sb + OFF_AH + woff, hi);
            sts32(sb + OFF_AL + woff, lo);
        }
    }
    // enc bias column (k=180 -> kt 11, lane k-part 2, regs 0&1)
    if (tid < 64) {
        int mt = tid >> 3, qq = tid & 7;
        uint32_t addr = sb + OFF_AH + (uint32_t)((((11 * 8 + mt) * 32 + ((qq << 2) | 2)) * 4) * 4);
        sts64(addr, 0x00003F80u, 0x00003F80u);
    }
    __syncthreads();  // Sx readers done before prefetch overwrites B region

    // chunk source table: 0..5 enc (gate c/2, half c&1), 6..8 dec (gate c-6)
    auto srcH = [&](int c) -> const uint4* {
        if (c < 6) return reinterpret_cast<const uint4*>(g_eBFh + (c >> 1) * EB_G + (c & 1) * 5376);
        return reinterpret_cast<const uint4*>(g_dBFh + (c - 6) * DB_G);
    };
    auto srcL = [&](int c) -> const uint4* {
        if (c < 6) return reinterpret_cast<const uint4*>(g_eBFl + (c >> 1) * EB_G + (c & 1) * 5376);
        return reinterpret_cast<const uint4*>(g_dBFl + (c - 6) * DB_G);
    };
    auto prefetch = [&](int c) {
        uint32_t dH = sb + OFF_B + (uint32_t)((c & 1) * CHUNK_B);
        uint32_t dL = dH + 21504;
        const uint4* sh = srcH(c);
        const uint4* sl = srcL(c);
        for (int i = tid; i < 1344; i += 256) {
            cp16(dH + (uint32_t)(i * 16), sh + i);
            cp16(dL + (uint32_t)(i * 16), sl + i);
        }
        CP_COMMIT();
    };

    prefetch(0);
    prefetch(1);

    float acc[48], sv[48];

    for (int c = 0; c < 9; ++c) {
        if (c < 8) { CP_WAIT1(); } else { CP_WAIT0(); }
        __syncthreads();  // chunk c visible; prior epilogue smem writes visible

        if (c == 0 || c == 2 || c == 4 || c >= 6) {
#pragma unroll
            for (int i = 0; i < 48; ++i) acc[i] = 0.f;
        }
        uint32_t abH, abL;
        if (c < 6) {
            abH = sb + OFF_AH + (uint32_t)((c & 1) * 24576);
            abL = sb + OFF_AL + (uint32_t)((c & 1) * 24576);
        } else {
            abH = sb + OFF_ADH;
            abL = sb + OFF_ADL;
        }
        uint32_t bbH = sb + OFF_B + (uint32_t)((c & 1) * CHUNK_B);
        chunk_mma(abH, abL, bbH, bbH + 21504, aoffb, boffb, acc);

        if (c == 5) __syncthreads();  // all enc-A readers done before dec-A scatter

        // epilogues
        if (c == 1 || c == 6) {
#pragma unroll
            for (int i = 0; i < 48; ++i) sv[i] = sigA(acc[i]);
        } else if (c == 3 || c == 7) {
#pragma unroll
            for (int i = 0; i < 48; ++i) sv[i] = sv[i] * tanhA(acc[i]);  // c-state
        } else if (c == 5) {
            // h1 = sig(sig(o)*tanh(c)) -> scatter into dec A frags (own-lane writes)
#pragma unroll
            for (int mi = 0; mi < 2; ++mi) {
#pragma unroll
                for (int ni = 0; ni < 6; ++ni) {
                    const float* a = acc + (mi * 6 + ni) * 4;
                    const float* s = sv + (mi * 6 + ni) * 4;
                    int nt = ng * 6 + ni;
                    uint32_t hi1, lo1, hi2, lo2;
                    if (nt == 11 && tig >= 1) {
                        hi1 = hi2 = (tig == 1) ? 0x00003F80u : 0u;  // dec bias col j=90
                        lo1 = lo2 = 0u;
                    } else {
                        float h0 = sigA(sigA(a[0]) * tanhA(s[0]));
                        float h1 = sigA(sigA(a[1]) * tanhA(s[1]));
                        float h2 = sigA(sigA(a[2]) * tanhA(s[2]));
                        float h3 = sigA(sigA(a[3]) * tanhA(s[3]));
                        packsplit2(h0, h1, hi1, lo1);
                        packsplit2(h2, h3, hi2, lo2);
                    }
                    int jp = nt * 4 + tig;
                    int ktd = jp >> 3, regb = ((jp >> 2) & 1) << 1;
                    int mtd = mg * 2 + mi;
                    uint32_t w = sb + OFF_ADH +
                        (uint32_t)(((((ktd * 8 + mtd) * 32 + lane) * 4) + regb) * 4);
                    sts64(w, hi1, hi2);
                    sts64(w + 24576, lo1, lo2);
                }
            }
        } else if (c == 8) {
            // h2 = sig(o)*tanh(c) -> g_h2
            float* hb = g_h2 + (size_t)b * (NT * NH) + (size_t)t0 * NH;
#pragma unroll
            for (int mi = 0; mi < 2; ++mi) {
#pragma unroll
                for (int ni = 0; ni < 6; ++ni) {
                    int nt = ng * 6 + ni;
                    if (nt == 11 && tig >= 1) continue;
                    const float* a = acc + (mi * 6 + ni) * 4;
                    const float* s = sv + (mi * 6 + ni) * 4;
                    int j0 = nt * 8 + 2 * tig;
                    int r1 = (mg * 2 + mi) * 16 + q, r2 = r1 + 8;
                    float v0 = sigA(a[0]) * tanhA(s[0]);
                    float v1 = sigA(a[1]) * tanhA(s[1]);
                    *reinterpret_cast<float2*>(hb + r1 * NH + j0) = make_float2(v0, v1);
                    if (r2 < 120) {
                        float v2 = sigA(a[2]) * tanhA(s[2]);
                        float v3 = sigA(a[3]) * tanhA(s[3]);
                        *reinterpret_cast<float2*>(hb + r2 * NH + j0) = make_float2(v2, v3);
                    }
                }
            }
        }

        __syncthreads();  // buf[c&1] readers done; epilogue smem writes published
        if (c + 2 < 9) prefetch(c + 2);
    }
}

// ===== output GEMM (k-split partials) =====
__global__ void __launch_bounds__(256, 1)
out_gemm_kernel(const float* __restrict__ W) {
    extern __shared__ float sm[];
    float* Hs = sm;           // 240*33
    float* Wt = sm + 7920;    // 240*44
    const int b0 = blockIdx.y * 32;
    const int k0 = blockIdx.x * (21600 / KS);
    const int tid = threadIdx.x, wi = tid >> 5, lane = tid & 31;

    float acc[40];
#pragma unroll
    for (int n = 0; n < 40; ++n) acc[n] = 0.f;

    for (int tile = 0; tile < (21600 / KS) / 240; ++tile) {
        const int kt = k0 + tile * 240;
        __syncthreads();
        for (int idx = tid; idx < 32 * 240; idx += 256) {
            int bb = idx / 240, k = idx - bb * 240;
            Hs[k * 33 + bb] = g_h2[(size_t)(b0 + bb) * 21600 + kt + k];
        }
        for (int idx = tid; idx < 40 * 240; idx += 256) {
            int n = idx / 240, k = idx - n * 240;
            Wt[k * 44 + n] = W[(size_t)n * 21600 + kt + k];
        }
        __syncthreads();
#pragma unroll 2
        for (int kk = 0; kk < 30; ++kk) {
            int k = wi * 30 + kk;
            float h = Hs[k * 33 + lane];
            const float4* wp = reinterpret_cast<const float4*>(Wt + k * 44);
#pragma unroll
            for (int n4 = 0; n4 < 10; ++n4) {
                float4 w = wp[n4];
                acc[n4 * 4 + 0] += h * w.x;
                acc[n4 * 4 + 1] += h * w.y;
                acc[n4 * 4 + 2] += h * w.z;
                acc[n4 * 4 + 3] += h * w.w;
            }
        }
    }
    __syncthreads();
    float* Rs = sm;
#pragma unroll
    for (int n = 0; n < 40; ++n) Rs[(wi * 32 + lane) * 40 + n] = acc[n];
    __syncthreads();
    for (int idx = tid; idx < 32 * 40; idx += 256) {
        int bb = idx / 40, n = idx - bb * 40;
        float s = 0.f;
#pragma unroll
        for (int w = 0; w < 8; ++w) s += Rs[(w * 32 + bb) * 40 + n];
        g_part[blockIdx.x * (NB * 40) + (b0 + bb) * 40 + n] = s;
    }
}

__global__ void softmax_kernel(const float* __restrict__ ob, float* __restrict__ out) {
    __shared__ float L[40];
    __shared__ float E[40];
    const int b = blockIdx.x, n = threadIdx.x;
    float s = 0.f;
#pragma unroll
    for (int ks = 0; ks < KS; ++ks) s += g_part[ks * (NB * 40) + b * 40 + n];
    s += ob[n];
    L[n] = s;
    __syncthreads();
    const int g0 = (n / 10) * 10;
    float mx = -1e30f;
#pragma unroll
    for (int i = 0; i < 10; ++i) mx = fmaxf(mx, L[g0 + i]);
    float e = __expf(s - mx);
    E[n] = e;
    __syncthreads();
    float sum = 0.f;
#pragma unroll
    for (int i = 0; i < 10; ++i) sum += E[g0 + i];
    out[b * 40 + n] = __fdividef(e, sum);
}

extern "C" void kernel_launch(void* const* d_in, const int* in_sizes, int n_in,
                              void* d_out, int out_size) {
    const float* x   = (const float*)d_in[0];
    const float* eW  = (const float*)d_in[1];
    const float* eb1 = (const float*)d_in[2];
    const float* eb2 = (const float*)d_in[3];
    const float* dW  = (const float*)d_in[4];
    const float* db1 = (const float*)d_in[5];
    const float* db2 = (const float*)d_in[6];
    const float* oW  = (const float*)d_in[7];
    const float* ob  = (const float*)d_in[8];
    float* out = (float*)d_out;

    cudaFuncSetAttribute(lstm_mma_kernel,
                         cudaFuncAttributeMaxDynamicSharedMemorySize, SMEM_LSTM);
    cudaFuncSetAttribute(out_gemm_kernel,
                         cudaFuncAttributeMaxDynamicSharedMemorySize, 73920);

    prep_kernel<<<162, 256>>>(eW, eb1, eb2, dW, db1, db2);
    lstm_mma_kernel<<<2048, 256, SMEM_LSTM>>>(x);
    out_gemm_kernel<<<dim3(KS, 32), 256, 73920>>>(oW);
    softmax_kernel<<<NB, 40>>>(ob, out);
}

// round 7
// speedup vs baseline: 2.8225x; 1.1838x over previous
#include <cuda_runtime.h>
#include <cuda_fp16.h>
#include <cstdint>

#define NB 1024
#define NT 240
#define NH 90
#define NF 180
#define KS 30

// frag-image sizes (u32 words)
#define EB_G (12*32*28)  // enc gate image (per hi/lo)
#define DB_G (6*32*28)   // dec gate image

// lstm smem layout (bytes)
#define OFF_AH  0        // enc A fp16 [12kt][8mt][32][16B] = 49152
#define OFF_ADH 0        // dec A fp16 [6kt][8][32][16B] = 24576 (reuse)
#define OFF_B   49152    // 2 x 43008 chunk buffers (Bhi 21504 | Blo 21504 each)
#define CHUNK_B 43008
#define SMEM_LSTM (OFF_B + 2*CHUNK_B)   // 135168

__device__ __align__(16) uint32_t g_eBFh[3*EB_G], g_eBFl[3*EB_G];
__device__ __align__(16) uint32_t g_dBFh[3*DB_G], g_dBFl[3*DB_G];
__device__ float g_h2[(size_t)NB*NT*NH];
__device__ float g_part[KS*NB*40];

// ---- helpers ----
static __device__ __forceinline__ uint32_t smem_u32(const void* p) {
    uint32_t a;
    asm("{ .reg .u64 t; cvta.to.shared.u64 t, %1; cvt.u32.u64 %0, t; }" : "=r"(a) : "l"(p));
    return a;
}
static __device__ __forceinline__ uint4 lds128(uint32_t a) {
    uint4 v;
    asm volatile("ld.shared.v4.b32 {%0,%1,%2,%3}, [%4];"
                 : "=r"(v.x), "=r"(v.y), "=r"(v.z), "=r"(v.w) : "r"(a));
    return v;
}
static __device__ __forceinline__ void sts32(uint32_t a, uint32_t v) {
    asm volatile("st.shared.b32 [%0], %1;" :: "r"(a), "r"(v));
}
static __device__ __forceinline__ void sts64(uint32_t a, uint32_t v0, uint32_t v1) {
    asm volatile("st.shared.v2.b32 [%0], {%1,%2};" :: "r"(a), "r"(v0), "r"(v1));
}
static __device__ __forceinline__ void sts128z(uint32_t a) {
    asm volatile("st.shared.v4.b32 [%0], {%1,%1,%1,%1};" :: "r"(a), "r"(0u));
}
static __device__ __forceinline__ void cp16(uint32_t saddr, const void* g) {
    asm volatile("{ .reg .u64 gp; cvta.to.global.u64 gp, %1;"
                 "  cp.async.cg.shared.global [%0], [gp], 16; }"
                 :: "r"(saddr), "l"(g) : "memory");
}
#define CP_COMMIT() asm volatile("cp.async.commit_group;" ::: "memory")
#define CP_WAIT1()  asm volatile("cp.async.wait_group 1;" ::: "memory")
#define CP_WAIT0()  asm volatile("cp.async.wait_group 0;" ::: "memory")

static __device__ __forceinline__ void mma4(float* c, const uint4& a, uint32_t b0, uint32_t b1) {
    asm volatile(
        "mma.sync.aligned.m16n8k16.row.col.f32.f16.f16.f32 "
        "{%0,%1,%2,%3}, {%4,%5,%6,%7}, {%8,%9}, {%0,%1,%2,%3};"
        : "+f"(c[0]), "+f"(c[1]), "+f"(c[2]), "+f"(c[3])
        : "r"(a.x), "r"(a.y), "r"(a.z), "r"(a.w), "r"(b0), "r"(b1));
}
static __device__ __forceinline__ float tanhA(float x) {
    float y;
    asm("tanh.approx.f32 %0, %1;" : "=f"(y) : "f"(x));
    return y;
}
static __device__ __forceinline__ float sigA(float x) {
    return fmaf(tanhA(0.5f * x), 0.5f, 0.5f);
}
// pack two floats to fp16x2 (single)
static __device__ __forceinline__ uint32_t packh2(float v0, float v1) {
    __half2 h = __floats2half2_rn(v0, v1);
    return *reinterpret_cast<uint32_t*>(&h);
}
// exact fp16 hi/lo split of two floats
static __device__ __forceinline__ void packsplit2h(float v0, float v1, uint32_t& hi, uint32_t& lo) {
    __half h0 = __float2half_rn(v0), h1 = __float2half_rn(v1);
    hi = (uint32_t)__half_as_ushort(h0) | ((uint32_t)__half_as_ushort(h1) << 16);
    __half l0 = __float2half_rn(v0 - __half2float(h0));
    __half l1 = __float2half_rn(v1 - __half2float(h1));
    lo = (uint32_t)__half_as_ushort(l0) | ((uint32_t)__half_as_ushort(l1) << 16);
}

#define MMA6(accp, A, B0, B1, B2) \
    mma4((accp) + 0,  A, B0.x, B0.y); mma4((accp) + 4,  A, B0.z, B0.w); \
    mma4((accp) + 8,  A, B1.x, B1.y); mma4((accp) + 12, A, B1.z, B1.w); \
    mma4((accp) + 16, A, B2.x, B2.y); mma4((accp) + 20, A, B2.z, B2.w);

// one 6-kt chunk: 2-pass (A·Bh + A·Bl), warp covers 2 mtiles x 6 ntiles
static __device__ __forceinline__ void chunk_mma(uint32_t abA, uint32_t bbH, uint32_t bbL,
                                                 uint32_t aoffb, uint32_t boffb, float* acc) {
#pragma unroll
    for (int kt = 0; kt < 6; ++kt) {
        uint32_t aa = abA + kt * 4096 + aoffb;
        uint4 a0 = lds128(aa), a1 = lds128(aa + 512);
        uint32_t bo = kt * 3584 + boffb;
        uint4 B0 = lds128(bbH + bo), B1 = lds128(bbH + bo + 16), B2 = lds128(bbH + bo + 32);
        uint4 C0 = lds128(bbL + bo), C1 = lds128(bbL + bo + 16), C2 = lds128(bbL + bo + 32);
        MMA6(acc,      a0, B0, B1, B2);
        MMA6(acc + 24, a1, B0, B1, B2);
        MMA6(acc,      a0, C0, C1, C2);
        MMA6(acc + 24, a1, C0, C1, C2);
    }
}

// ===== prep: pack weights (exact fp16 hi/lo split, bias folded) into frag images =====
__global__ void prep_kernel(const float* __restrict__ eW, const float* __restrict__ eb1,
                            const float* __restrict__ eb2, const float* __restrict__ dW,
                            const float* __restrict__ db1, const float* __restrict__ db2) {
    int idx = blockIdx.x * 256 + threadIdx.x;
    const int goff[3] = {0, 180, 270};  // i, g, o (f gate skipped: c0 = 0)
    if (idx < 3 * 96 * 96) {
        int gate = idx / (96 * 96), rem = idx % (96 * 96);
        int n = rem / 96, kp = rem % 96;
        int k = 2 * kp;
        float v0 = 0.f, v1 = 0.f;
        if (n < NH) {
            if (k < NF) { v0 = eW[(goff[gate] + n) * NF + k]; v1 = eW[(goff[gate] + n) * NF + k + 1]; }
            else if (k == NF) v0 = eb1[goff[gate] + n] + eb2[goff[gate] + n];
        }
        uint32_t hi, lo; packsplit2h(v0, v1, hi, lo);
        int pos = ((kp >> 3) * 32 + ((n & 7) << 2) + (kp & 3)) * 28 + (n >> 3) * 2 + ((kp >> 2) & 1);
        g_eBFh[gate * EB_G + pos] = hi;
        g_eBFl[gate * EB_G + pos] = lo;
        return;
    }
    int j = idx - 3 * 96 * 96;
    if (j < 3 * 96 * 48) {
        int gate = j / (96 * 48), rem = j % (96 * 48);
        int n = rem / 48, kp = rem % 48;
        int k = 2 * kp;
        float v0 = 0.f, v1 = 0.f;
        if (n < NH) {
            if (k < NH) { v0 = dW[(goff[gate] + n) * NH + k]; v1 = dW[(goff[gate] + n) * NH + k + 1]; }
            else if (k == NH) v0 = db1[goff[gate] + n] + db2[goff[gate] + n];
        }
        uint32_t hi, lo; packsplit2h(v0, v1, hi, lo);
        int pos = ((kp >> 3) * 32 + ((n & 7) << 2) + (kp & 3)) * 28 + (n >> 3) * 2 + ((kp >> 2) & 1);
        g_dBFh[gate * DB_G + pos] = hi;
        g_dBFl[gate * DB_G + pos] = lo;
    }
}

// ===== fused LSTM: fp16 mma.sync 2-pass + cp.async pipelined B chunks =====
__global__ void __launch_bounds__(256, 1)
lstm_mma_kernel(const float* __restrict__ x) {
    extern __shared__ char smem[];
    const uint32_t sb = smem_u32(smem);
    const int tid = threadIdx.x, wid = tid >> 5, lane = tid & 31;
    const int b = blockIdx.x >> 1, th = blockIdx.x & 1;
    const int t0 = th * 120;
    const int tig = lane & 3, q = lane >> 2;
    const int mg = wid >> 1, ng = wid & 1;
    const uint32_t aoffb = (uint32_t)(mg * 2 * 512 + lane * 16);
    const uint32_t boffb = (uint32_t)(lane * 112 + ng * 48);

    // zero enc A region (49152B)
    for (int i = tid; i < 3072; i += 256) sts128z(sb + (uint32_t)(i * 16));

    // stage x coalesced, scatter fp16 into enc A frags (two 90-feature phases)
    float* Sx = reinterpret_cast<float*>(smem + OFF_B);
    for (int ph = 0; ph < 2; ++ph) {
        __syncthreads();
        const float* xb = x + ((size_t)b * NF + ph * 90) * NT + t0;
        for (int i = tid; i < 2700; i += 256) {
            int f = i / 30, c = i % 30;
            const float4 v = *reinterpret_cast<const float4*>(xb + f * NT + c * 4);
            *reinterpret_cast<float4*>(Sx + f * 120 + c * 4) = v;
        }
        __syncthreads();
        for (int i = tid; i < 5400; i += 256) {
            int r = i / 45, kpl = i % 45;
            int kp = ph * 45 + kpl, fp = 2 * kpl;
            uint32_t hv = packh2(Sx[fp * 120 + r], Sx[(fp + 1) * 120 + r]);
            int rr = r & 15, mt = r >> 4;
            int lne = ((rr & 7) << 2) | (kp & 3);
            int reg = (((kp >> 2) & 1) << 1) | (rr >> 3);
            uint32_t woff = (uint32_t)(((((kp >> 3) * 8 + mt) * 32 + lne) * 4 + reg) * 4);
            sts32(sb + OFF_AH + woff, hv);
        }
    }
    // enc bias column (k=180 -> kt 11, lane k-part 2, regs 0&1): fp16 1.0 = 0x3C00
    if (tid < 64) {
        int mt = tid >> 3, qq = tid & 7;
        uint32_t addr = sb + OFF_AH + (uint32_t)((((11 * 8 + mt) * 32 + ((qq << 2) | 2)) * 4) * 4);
        sts64(addr, 0x00003C00u, 0x00003C00u);
    }
    __syncthreads();  // Sx readers done before prefetch overwrites B region

    auto srcH = [&](int c) -> const uint4* {
        if (c < 6) return reinterpret_cast<const uint4*>(g_eBFh + (c >> 1) * EB_G + (c & 1) * 5376);
        return reinterpret_cast<const uint4*>(g_dBFh + (c - 6) * DB_G);
    };
    auto srcL = [&](int c) -> const uint4* {
        if (c < 6) return reinterpret_cast<const uint4*>(g_eBFl + (c >> 1) * EB_G + (c & 1) * 5376);
        return reinterpret_cast<const uint4*>(g_dBFl + (c - 6) * DB_G);
    };
    auto prefetch = [&](int c) {
        uint32_t dH = sb + OFF_B + (uint32_t)((c & 1) * CHUNK_B);
        uint32_t dL = dH + 21504;
        const uint4* sh = srcH(c);
        const uint4* sl = srcL(c);
        for (int i = tid; i < 1344; i += 256) {
            cp16(dH + (uint32_t)(i * 16), sh + i);
            cp16(dL + (uint32_t)(i * 16), sl + i);
        }
        CP_COMMIT();
    };

    prefetch(0);
    prefetch(1);

    float acc[48], sv[48];

    for (int c = 0; c < 9; ++c) {
        if (c < 8) { CP_WAIT1(); } else { CP_WAIT0(); }
        __syncthreads();  // chunk c visible; prior epilogue smem writes visible

        if (c == 0 || c == 2 || c == 4 || c >= 6) {
#pragma unroll
            for (int i = 0; i < 48; ++i) acc[i] = 0.f;
        }
        uint32_t abA = (c < 6) ? (sb + OFF_AH + (uint32_t)((c & 1) * 24576))
                               : (sb + OFF_ADH);
        uint32_t bbH = sb + OFF_B + (uint32_t)((c & 1) * CHUNK_B);
        chunk_mma(abA, bbH, bbH + 21504, aoffb, boffb, acc);

        if (c == 5) __syncthreads();  // all enc-A readers done before dec-A scatter

        // epilogues
        if (c == 1 || c == 6) {
#pragma unroll
            for (int i = 0; i < 48; ++i) sv[i] = sigA(acc[i]);
        } else if (c == 3 || c == 7) {
#pragma unroll
            for (int i = 0; i < 48; ++i) sv[i] = sv[i] * tanhA(acc[i]);  // c-state
        } else if (c == 5) {
            // h1 = sig(sig(o)*tanh(c)) -> scatter fp16 into dec A frags (own-lane writes)
#pragma unroll
            for (int mi = 0; mi < 2; ++mi) {
#pragma unroll
                for (int ni = 0; ni < 6; ++ni) {
                    const float* a = acc + (mi * 6 + ni) * 4;
                    const float* s = sv + (mi * 6 + ni) * 4;
                    int nt = ng * 6 + ni;
                    uint32_t hv1, hv2;
                    if (nt == 11 && tig >= 1) {
                        hv1 = hv2 = (tig == 1) ? 0x00003C00u : 0u;  // dec bias col j=90
                    } else {
                        hv1 = packh2(sigA(sigA(a[0]) * tanhA(s[0])),
                                     sigA(sigA(a[1]) * tanhA(s[1])));
                        hv2 = packh2(sigA(sigA(a[2]) * tanhA(s[2])),
                                     sigA(sigA(a[3]) * tanhA(s[3])));
                    }
                    int jp = nt * 4 + tig;
                    int ktd = jp >> 3, regb = ((jp >> 2) & 1) << 1;
                    int mtd = mg * 2 + mi;
                    uint32_t w = sb + OFF_ADH +
                        (uint32_t)(((((ktd * 8 + mtd) * 32 + lane) * 4) + regb) * 4);
                    sts64(w, hv1, hv2);
                }
            }
        } else if (c == 8) {
            // h2 = sig(o)*tanh(c) -> g_h2
            float* hb = g_h2 + (size_t)b * (NT * NH) + (size_t)t0 * NH;
#pragma unroll
            for (int mi = 0; mi < 2; ++mi) {
#pragma unroll
                for (int ni = 0; ni < 6; ++ni) {
                    int nt = ng * 6 + ni;
                    if (nt == 11 && tig >= 1) continue;
                    const float* a = acc + (mi * 6 + ni) * 4;
                    const float* s = sv + (mi * 6 + ni) * 4;
                    int j0 = nt * 8 + 2 * tig;
                    int r1 = (mg * 2 + mi) * 16 + q, r2 = r1 + 8;
                    float v0 = sigA(a[0]) * tanhA(s[0]);
                    float v1 = sigA(a[1]) * tanhA(s[1]);
                    *reinterpret_cast<float2*>(hb + r1 * NH + j0) = make_float2(v0, v1);
                    if (r2 < 120) {
                        float v2 = sigA(a[2]) * tanhA(s[2]);
                        float v3 = sigA(a[3]) * tanhA(s[3]);
                        *reinterpret_cast<float2*>(hb + r2 * NH + j0) = make_float2(v2, v3);
                    }
                }
            }
        }

        __syncthreads();  // buf[c&1] readers done; epilogue smem writes published
        if (c + 2 < 9) prefetch(c + 2);
    }
}

// ===== output GEMM (k-split partials) =====
__global__ void __launch_bounds__(256, 1)
out_gemm_kernel(const float* __restrict__ W) {
    extern __shared__ float sm[];
    float* Hs = sm;           // 240*33
    float* Wt = sm + 7920;    // 240*44
    const int b0 = blockIdx.y * 32;
    const int k0 = blockIdx.x * (21600 / KS);
    const int tid = threadIdx.x, wi = tid >> 5, lane = tid & 31;

    float acc[40];
#pragma unroll
    for (int n = 0; n < 40; ++n) acc[n] = 0.f;

    for (int tile = 0; tile < (21600 / KS) / 240; ++tile) {
        const int kt = k0 + tile * 240;
        __syncthreads();
        for (int idx = tid; idx < 32 * 240; idx += 256) {
            int bb = idx / 240, k = idx - bb * 240;
            Hs[k * 33 + bb] = g_h2[(size_t)(b0 + bb) * 21600 + kt + k];
        }
        for (int idx = tid; idx < 40 * 240; idx += 256) {
            int n = idx / 240, k = idx - n * 240;
            Wt[k * 44 + n] = W[(size_t)n * 21600 + kt + k];
        }
        __syncthreads();
#pragma unroll 2
        for (int kk = 0; kk < 30; ++kk) {
            int k = wi * 30 + kk;
            float h = Hs[k * 33 + lane];
            const float4* wp = reinterpret_cast<const float4*>(Wt + k * 44);
#pragma unroll
            for (int n4 = 0; n4 < 10; ++n4) {
                float4 w = wp[n4];
                acc[n4 * 4 + 0] += h * w.x;
                acc[n4 * 4 + 1] += h * w.y;
                acc[n4 * 4 + 2] += h * w.z;
                acc[n4 * 4 + 3] += h * w.w;
            }
        }
    }
    __syncthreads();
    float* Rs = sm;
#pragma unroll
    for (int n = 0; n < 40; ++n) Rs[(wi * 32 + lane) * 40 + n] = acc[n];
    __syncthreads();
    for (int idx = tid; idx < 32 * 40; idx += 256) {
        int bb = idx / 40, n = idx - bb * 40;
        float s = 0.f;
#pragma unroll
        for (int w = 0; w < 8; ++w) s += Rs[(w * 32 + bb) * 40 + n];
        g_part[blockIdx.x * (NB * 40) + (b0 + bb) * 40 + n] = s;
    }
}

__global__ void softmax_kernel(const float* __restrict__ ob, float* __restrict__ out) {
    __shared__ float L[40];
    __shared__ float E[40];
    const int b = blockIdx.x, n = threadIdx.x;
    float s = 0.f;
#pragma unroll
    for (int ks = 0; ks < KS; ++ks) s += g_part[ks * (NB * 40) + b * 40 + n];
    s += ob[n];
    L[n] = s;
    __syncthreads();
    const int g0 = (n / 10) * 10;
    float mx = -1e30f;
#pragma unroll
    for (int i = 0; i < 10; ++i) mx = fmaxf(mx, L[g0 + i]);
    float e = __expf(s - mx);
    E[n] = e;
    __syncthreads();
    float sum = 0.f;
#pragma unroll
    for (int i = 0; i < 10; ++i) sum += E[g0 + i];
    out[b * 40 + n] = __fdividef(e, sum);
}

extern "C" void kernel_launch(void* const* d_in, const int* in_sizes, int n_in,
                              void* d_out, int out_size) {
    const float* x   = (const float*)d_in[0];
    const float* eW  = (const float*)d_in[1];
    const float* eb1 = (const float*)d_in[2];
    const float* eb2 = (const float*)d_in[3];
    const float* dW  = (const float*)d_in[4];
    const float* db1 = (const float*)d_in[5];
    const float* db2 = (const float*)d_in[6];
    const float* oW  = (const float*)d_in[7];
    const float* ob  = (const float*)d_in[8];
    float* out = (float*)d_out;

    cudaFuncSetAttribute(lstm_mma_kernel,
                         cudaFuncAttributeMaxDynamicSharedMemorySize, SMEM_LSTM);
    cudaFuncSetAttribute(out_gemm_kernel,
                         cudaFuncAttributeMaxDynamicSharedMemorySize, 73920);

    prep_kernel<<<162, 256>>>(eW, eb1, eb2, dW, db1, db2);
    lstm_mma_kernel<<<2048, 256, SMEM_LSTM>>>(x);
    out_gemm_kernel<<<dim3(KS, 32), 256, 73920>>>(oW);
    softmax_kernel<<<NB, 40>>>(ob, out);
}

// round 8
// speedup vs baseline: 3.5385x; 1.2537x over previous
#include <cuda_runtime.h>
#include <cuda_fp16.h>
#include <cstdint>

#define NB 1024
#define NT 240
#define NH 90
#define NF 180
#define KS 30

// frag-image sizes (u32 words)
#define EB_G (12*32*28)  // enc gate image
#define DB_G (6*32*28)   // dec gate image

// lstm smem layout (bytes)
#define OFF_AH  0        // enc A fp16 [12kt][8mt][32][16B] = 49152
#define OFF_ADH 0        // dec A fp16 [6kt][8][32][16B] = 24576 (reuse)
#define OFF_B   49152    // 2 x 21504 chunk buffers
#define CHUNK_B 21504
#define SMEM_LSTM (OFF_B + 43200)   // staging needs 43200B (> 2*21504)

__device__ __align__(16) uint32_t g_eBF[3*EB_G];
__device__ __align__(16) uint32_t g_dBF[3*DB_G];
__device__ __half g_h2h[(size_t)NB*NT*NH];
__device__ float g_part[KS*NB*40];

// ---- helpers ----
static __device__ __forceinline__ uint32_t smem_u32(const void* p) {
    uint32_t a;
    asm("{ .reg .u64 t; cvta.to.shared.u64 t, %1; cvt.u32.u64 %0, t; }" : "=r"(a) : "l"(p));
    return a;
}
static __device__ __forceinline__ uint4 lds128(uint32_t a) {
    uint4 v;
    asm volatile("ld.shared.v4.b32 {%0,%1,%2,%3}, [%4];"
                 : "=r"(v.x), "=r"(v.y), "=r"(v.z), "=r"(v.w) : "r"(a));
    return v;
}
static __device__ __forceinline__ void sts32(uint32_t a, uint32_t v) {
    asm volatile("st.shared.b32 [%0], %1;" :: "r"(a), "r"(v));
}
static __device__ __forceinline__ void sts64(uint32_t a, uint32_t v0, uint32_t v1) {
    asm volatile("st.shared.v2.b32 [%0], {%1,%2};" :: "r"(a), "r"(v0), "r"(v1));
}
static __device__ __forceinline__ void sts128z(uint32_t a) {
    asm volatile("st.shared.v4.b32 [%0], {%1,%1,%1,%1};" :: "r"(a), "r"(0u));
}
static __device__ __forceinline__ void cp16(uint32_t saddr, const void* g) {
    asm volatile("{ .reg .u64 gp; cvta.to.global.u64 gp, %1;"
                 "  cp.async.cg.shared.global [%0], [gp], 16; }"
                 :: "r"(saddr), "l"(g) : "memory");
}
#define CP_COMMIT() asm volatile("cp.async.commit_group;" ::: "memory")
#define CP_WAIT1()  asm volatile("cp.async.wait_group 1;" ::: "memory")
#define CP_WAIT0()  asm volatile("cp.async.wait_group 0;" ::: "memory")

static __device__ __forceinline__ void mma4(float* c, const uint4& a, uint32_t b0, uint32_t b1) {
    asm volatile(
        "mma.sync.aligned.m16n8k16.row.col.f32.f16.f16.f32 "
        "{%0,%1,%2,%3}, {%4,%5,%6,%7}, {%8,%9}, {%0,%1,%2,%3};"
        : "+f"(c[0]), "+f"(c[1]), "+f"(c[2]), "+f"(c[3])
        : "r"(a.x), "r"(a.y), "r"(a.z), "r"(a.w), "r"(b0), "r"(b1));
}
static __device__ __forceinline__ float tanhA(float x) {
    float y;
    asm("tanh.approx.f32 %0, %1;" : "=f"(y) : "f"(x));
    return y;
}
static __device__ __forceinline__ float sigA(float x) {
    return fmaf(tanhA(0.5f * x), 0.5f, 0.5f);
}
static __device__ __forceinline__ uint32_t packh2(float v0, float v1) {
    __half2 h = __floats2half2_rn(v0, v1);
    return *reinterpret_cast<uint32_t*>(&h);
}

#define MMA6(accp, A, B0, B1, B2) \
    mma4((accp) + 0,  A, B0.x, B0.y); mma4((accp) + 4,  A, B0.z, B0.w); \
    mma4((accp) + 8,  A, B1.x, B1.y); mma4((accp) + 12, A, B1.z, B1.w); \
    mma4((accp) + 16, A, B2.x, B2.y); mma4((accp) + 20, A, B2.z, B2.w);

// one 6-kt chunk, single fp16 pass; warp covers 2 mtiles x 6 ntiles
static __device__ __forceinline__ void chunk_mma(uint32_t abA, uint32_t bb,
                                                 uint32_t aoffb, uint32_t boffb, float* acc) {
#pragma unroll
    for (int kt = 0; kt < 6; ++kt) {
        uint32_t aa = abA + kt * 4096 + aoffb;
        uint4 a0 = lds128(aa), a1 = lds128(aa + 512);
        uint32_t bo = kt * 3584 + boffb;
        uint4 B0 = lds128(bb + bo), B1 = lds128(bb + bo + 16), B2 = lds128(bb + bo + 32);
        MMA6(acc,      a0, B0, B1, B2);
        MMA6(acc + 24, a1, B0, B1, B2);
    }
}

// ===== prep: pack fp16 weights (bias folded) into frag-major images =====
__global__ void prep_kernel(const float* __restrict__ eW, const float* __restrict__ eb1,
                            const float* __restrict__ eb2, const float* __restrict__ dW,
                            const float* __restrict__ db1, const float* __restrict__ db2) {
    int idx = blockIdx.x * 256 + threadIdx.x;
    const int goff[3] = {0, 180, 270};  // i, g, o (f gate skipped: c0 = 0)
    if (idx < 3 * 96 * 96) {
        int gate = idx / (96 * 96), rem = idx % (96 * 96);
        int n = rem / 96, kp = rem % 96;
        int k = 2 * kp;
        float v0 = 0.f, v1 = 0.f;
        if (n < NH) {
            if (k < NF) { v0 = eW[(goff[gate] + n) * NF + k]; v1 = eW[(goff[gate] + n) * NF + k + 1]; }
            else if (k == NF) v0 = eb1[goff[gate] + n] + eb2[goff[gate] + n];
        }
        int pos = ((kp >> 3) * 32 + ((n & 7) << 2) + (kp & 3)) * 28 + (n >> 3) * 2 + ((kp >> 2) & 1);
        g_eBF[gate * EB_G + pos] = packh2(v0, v1);
        return;
    }
    int j = idx - 3 * 96 * 96;
    if (j < 3 * 96 * 48) {
        int gate = j / (96 * 48), rem = j % (96 * 48);
        int n = rem / 48, kp = rem % 48;
        int k = 2 * kp;
        float v0 = 0.f, v1 = 0.f;
        if (n < NH) {
            if (k < NH) { v0 = dW[(goff[gate] + n) * NH + k]; v1 = dW[(goff[gate] + n) * NH + k + 1]; }
            else if (k == NH) v0 = db1[goff[gate] + n] + db2[goff[gate] + n];
        }
        int pos = ((kp >> 3) * 32 + ((n & 7) << 2) + (kp & 3)) * 28 + (n >> 3) * 2 + ((kp >> 2) & 1);
        g_dBF[gate * DB_G + pos] = packh2(v0, v1);
    }
}

// ===== fused LSTM: single-pass fp16 mma.sync + cp.async pipelined B chunks =====
__global__ void __launch_bounds__(256, 1)
lstm_mma_kernel(const float* __restrict__ x) {
    extern __shared__ char smem[];
    const uint32_t sb = smem_u32(smem);
    const int tid = threadIdx.x, wid = tid >> 5, lane = tid & 31;
    const int b = blockIdx.x >> 1, th = blockIdx.x & 1;
    const int t0 = th * 120;
    const int tig = lane & 3, q = lane >> 2;
    const int mg = wid >> 1, ng = wid & 1;
    const uint32_t aoffb = (uint32_t)(mg * 2 * 512 + lane * 16);
    const uint32_t boffb = (uint32_t)(lane * 112 + ng * 48);

    // zero enc A region (49152B)
    for (int i = tid; i < 3072; i += 256) sts128z(sb + (uint32_t)(i * 16));

    // stage x coalesced, scatter fp16 into enc A frags (two 90-feature phases)
    float* Sx = reinterpret_cast<float*>(smem + OFF_B);
    for (int ph = 0; ph < 2; ++ph) {
        __syncthreads();
        const float* xb = x + ((size_t)b * NF + ph * 90) * NT + t0;
        for (int i = tid; i < 2700; i += 256) {
            int f = i / 30, c = i % 30;
            const float4 v = *reinterpret_cast<const float4*>(xb + f * NT + c * 4);
            *reinterpret_cast<float4*>(Sx + f * 120 + c * 4) = v;
        }
        __syncthreads();
        for (int i = tid; i < 5400; i += 256) {
            int r = i / 45, kpl = i % 45;
            int kp = ph * 45 + kpl, fp = 2 * kpl;
            uint32_t hv = packh2(Sx[fp * 120 + r], Sx[(fp + 1) * 120 + r]);
            int rr = r & 15, mt = r >> 4;
            int lne = ((rr & 7) << 2) | (kp & 3);
            int reg = (((kp >> 2) & 1) << 1) | (rr >> 3);
            uint32_t woff = (uint32_t)(((((kp >> 3) * 8 + mt) * 32 + lne) * 4 + reg) * 4);
            sts32(sb + OFF_AH + woff, hv);
        }
    }
    // enc bias column (k=180 -> kt 11, lane k-part 2, regs 0&1): fp16 1.0
    if (tid < 64) {
        int mt = tid >> 3, qq = tid & 7;
        uint32_t addr = sb + OFF_AH + (uint32_t)((((11 * 8 + mt) * 32 + ((qq << 2) | 2)) * 4) * 4);
        sts64(addr, 0x00003C00u, 0x00003C00u);
    }
    __syncthreads();  // Sx readers done before prefetch overwrites B region

    auto src = [&](int c) -> const uint4* {
        if (c < 6) return reinterpret_cast<const uint4*>(g_eBF + (c >> 1) * EB_G + (c & 1) * 5376);
        return reinterpret_cast<const uint4*>(g_dBF + (c - 6) * DB_G);
    };
    auto prefetch = [&](int c) {
        uint32_t d = sb + OFF_B + (uint32_t)((c & 1) * CHUNK_B);
        const uint4* s = src(c);
        for (int i = tid; i < 1344; i += 256) cp16(d + (uint32_t)(i * 16), s + i);
        CP_COMMIT();
    };

    prefetch(0);
    prefetch(1);

    float acc[48], sv[48];

    for (int c = 0; c < 9; ++c) {
        if (c < 8) { CP_WAIT1(); } else { CP_WAIT0(); }
        __syncthreads();  // chunk c visible; prior epilogue smem writes visible

        if (c == 0 || c == 2 || c == 4 || c >= 6) {
#pragma unroll
            for (int i = 0; i < 48; ++i) acc[i] = 0.f;
        }
        uint32_t abA = (c < 6) ? (sb + OFF_AH + (uint32_t)((c & 1) * 24576))
                               : (sb + OFF_ADH);
        uint32_t bb = sb + OFF_B + (uint32_t)((c & 1) * CHUNK_B);
        chunk_mma(abA, bb, aoffb, boffb, acc);

        if (c == 5) __syncthreads();  // all enc-A readers done before dec-A scatter

        // epilogues
        if (c == 1 || c == 6) {
#pragma unroll
            for (int i = 0; i < 48; ++i) sv[i] = sigA(acc[i]);
        } else if (c == 3 || c == 7) {
#pragma unroll
            for (int i = 0; i < 48; ++i) sv[i] = sv[i] * tanhA(acc[i]);  // c-state
        } else if (c == 5) {
            // h1 = sig(sig(o)*tanh(c)) -> scatter fp16 into dec A frags (own-lane writes)
#pragma unroll
            for (int mi = 0; mi < 2; ++mi) {
#pragma unroll
                for (int ni = 0; ni < 6; ++ni) {
                    const float* a = acc + (mi * 6 + ni) * 4;
                    const float* s = sv + (mi * 6 + ni) * 4;
                    int nt = ng * 6 + ni;
                    uint32_t hv1, hv2;
                    if (nt == 11 && tig >= 1) {
                        hv1 = hv2 = (tig == 1) ? 0x00003C00u : 0u;  // dec bias col j=90
                    } else {
                        hv1 = packh2(sigA(sigA(a[0]) * tanhA(s[0])),
                                     sigA(sigA(a[1]) * tanhA(s[1])));
                        hv2 = packh2(sigA(sigA(a[2]) * tanhA(s[2])),
                                     sigA(sigA(a[3]) * tanhA(s[3])));
                    }
                    int jp = nt * 4 + tig;
                    int ktd = jp >> 3, regb = ((jp >> 2) & 1) << 1;
                    int mtd = mg * 2 + mi;
                    uint32_t w = sb + OFF_ADH +
                        (uint32_t)(((((ktd * 8 + mtd) * 32 + lane) * 4) + regb) * 4);
                    sts64(w, hv1, hv2);
                }
            }
        } else if (c == 8) {
            // h2 = sig(o)*tanh(c) -> g_h2h (fp16)
            __half* hb = g_h2h + (size_t)b * (NT * NH) + (size_t)t0 * NH;
#pragma unroll
            for (int mi = 0; mi < 2; ++mi) {
#pragma unroll
                for (int ni = 0; ni < 6; ++ni) {
                    int nt = ng * 6 + ni;
                    if (nt == 11 && tig >= 1) continue;
                    const float* a = acc + (mi * 6 + ni) * 4;
                    const float* s = sv + (mi * 6 + ni) * 4;
                    int j0 = nt * 8 + 2 * tig;
                    int r1 = (mg * 2 + mi) * 16 + q, r2 = r1 + 8;
                    uint32_t p1 = packh2(sigA(a[0]) * tanhA(s[0]),
                                         sigA(a[1]) * tanhA(s[1]));
                    *reinterpret_cast<uint32_t*>(hb + r1 * NH + j0) = p1;
                    if (r2 < 120) {
                        uint32_t p2 = packh2(sigA(a[2]) * tanhA(s[2]),
                                             sigA(a[3]) * tanhA(s[3]));
                        *reinterpret_cast<uint32_t*>(hb + r2 * NH + j0) = p2;
                    }
                }
            }
        }

        __syncthreads();  // buf[c&1] readers done; epilogue smem writes published
        if (c + 2 < 9) prefetch(c + 2);
    }
}

// ===== output GEMM (k-split partials, h2 in fp16) =====
__global__ void __launch_bounds__(256, 1)
out_gemm_kernel(const float* __restrict__ W) {
    extern __shared__ float sm[];
    float* Hs = sm;           // 240*33
    float* Wt = sm + 7920;    // 240*44
    const int b0 = blockIdx.y * 32;
    const int k0 = blockIdx.x * (21600 / KS);
    const int tid = threadIdx.x, wi = tid >> 5, lane = tid & 31;

    float acc[40];
#pragma unroll
    for (int n = 0; n < 40; ++n) acc[n] = 0.f;

    for (int tile = 0; tile < (21600 / KS) / 240; ++tile) {
        const int kt = k0 + tile * 240;
        __syncthreads();
        for (int idx = tid; idx < 32 * 120; idx += 256) {
            int bb = idx / 120, k2 = idx - bb * 120;
            __half2 h = *reinterpret_cast<const __half2*>(
                g_h2h + (size_t)(b0 + bb) * 21600 + kt + 2 * k2);
            float2 f = __half22float2(h);
            Hs[(2 * k2) * 33 + bb] = f.x;
            Hs[(2 * k2 + 1) * 33 + bb] = f.y;
        }
        for (int idx = tid; idx < 40 * 240; idx += 256) {
            int n = idx / 240, k = idx - n * 240;
            Wt[k * 44 + n] = W[(size_t)n * 21600 + kt + k];
        }
        __syncthreads();
#pragma unroll 2
        for (int kk = 0; kk < 30; ++kk) {
            int k = wi * 30 + kk;
            float h = Hs[k * 33 + lane];
            const float4* wp = reinterpret_cast<const float4*>(Wt + k * 44);
#pragma unroll
            for (int n4 = 0; n4 < 10; ++n4) {
                float4 w = wp[n4];
                acc[n4 * 4 + 0] += h * w.x;
                acc[n4 * 4 + 1] += h * w.y;
                acc[n4 * 4 + 2] += h * w.z;
                acc[n4 * 4 + 3] += h * w.w;
            }
        }
    }
    __syncthreads();
    float* Rs = sm;
#pragma unroll
    for (int n = 0; n < 40; ++n) Rs[(wi * 32 + lane) * 40 + n] = acc[n];
    __syncthreads();
    for (int idx = tid; idx < 32 * 40; idx += 256) {
        int bb = idx / 40, n = idx - bb * 40;
        float s = 0.f;
#pragma unroll
        for (int w = 0; w < 8; ++w) s += Rs[(w * 32 + bb) * 40 + n];
        g_part[blockIdx.x * (NB * 40) + (b0 + bb) * 40 + n] = s;
    }
}

__global__ void softmax_kernel(const float* __restrict__ ob, float* __restrict__ out) {
    __shared__ float L[40];
    __shared__ float E[40];
    const int b = blockIdx.x, n = threadIdx.x;
    float s = 0.f;
#pragma unroll
    for (int ks = 0; ks < KS; ++ks) s += g_part[ks * (NB * 40) + b * 40 + n];
    s += ob[n];
    L[n] = s;
    __syncthreads();
    const int g0 = (n / 10) * 10;
    float mx = -1e30f;
#pragma unroll
    for (int i = 0; i < 10; ++i) mx = fmaxf(mx, L[g0 + i]);
    float e = __expf(s - mx);
    E[n] = e;
    __syncthreads();
    float sum = 0.f;
#pragma unroll
    for (int i = 0; i < 10; ++i) sum += E[g0 + i];
    out[b * 40 + n] = __fdividef(e, sum);
}

extern "C" void kernel_launch(void* const* d_in, const int* in_sizes, int n_in,
                              void* d_out, int out_size) {
    const float* x   = (const float*)d_in[0];
    const float* eW  = (const float*)d_in[1];
    const float* eb1 = (const float*)d_in[2];
    const float* eb2 = (const float*)d_in[3];
    const float* dW  = (const float*)d_in[4];
    const float* db1 = (const float*)d_in[5];
    const float* db2 = (const float*)d_in[6];
    const float* oW  = (const float*)d_in[7];
    const float* ob  = (const float*)d_in[8];
    float* out = (float*)d_out;

    cudaFuncSetAttribute(lstm_mma_kernel,
                         cudaFuncAttributeMaxDynamicSharedMemorySize, SMEM_LSTM);
    cudaFuncSetAttribute(out_gemm_kernel,
                         cudaFuncAttributeMaxDynamicSharedMemorySize, 73920);

    prep_kernel<<<162, 256>>>(eW, eb1, eb2, dW, db1, db2);
    lstm_mma_kernel<<<2048, 256, SMEM_LSTM>>>(x);
    out_gemm_kernel<<<dim3(KS, 32), 256, 73920>>>(oW);
    softmax_kernel<<<NB, 40>>>(ob, out);
}

// round 9
// speedup vs baseline: 4.0162x; 1.1350x over previous
#include <cuda_runtime.h>
#include <cuda_fp16.h>
#include <cstdint>

#define NB 1024
#define NT 240
#define NH 90
#define NF 180
#define KS 30

typedef unsigned long long ull;

// frag-image sizes (u32 words)
#define EB_G (12*32*28)  // enc gate image
#define DB_G (6*32*28)   // dec gate image

// lstm smem layout (bytes)
#define OFF_AH  0        // enc A fp16 [12kt][8mt][32][16B] = 49152
#define OFF_ADH 0        // dec A fp16 [6kt][8][32][16B] = 24576 (reuse)
#define OFF_B   49152    // 2 x 21504 chunk buffers
#define CHUNK_B 21504
#define SMEM_LSTM (OFF_B + 43200)   // 92352: x staging needs 43200B

__device__ __align__(16) uint32_t g_eBF[3*EB_G];
__device__ __align__(16) uint32_t g_dBF[3*DB_G];
__device__ __half g_h2h[(size_t)NB*NT*NH];
__device__ float g_part[KS*NB*40];

// ---- helpers ----
static __device__ __forceinline__ uint32_t smem_u32(const void* p) {
    uint32_t a;
    asm("{ .reg .u64 t; cvta.to.shared.u64 t, %1; cvt.u32.u64 %0, t; }" : "=r"(a) : "l"(p));
    return a;
}
static __device__ __forceinline__ uint4 lds128(uint32_t a) {
    uint4 v;
    asm volatile("ld.shared.v4.b32 {%0,%1,%2,%3}, [%4];"
                 : "=r"(v.x), "=r"(v.y), "=r"(v.z), "=r"(v.w) : "r"(a));
    return v;
}
static __device__ __forceinline__ void sts32(uint32_t a, uint32_t v) {
    asm volatile("st.shared.b32 [%0], %1;" :: "r"(a), "r"(v));
}
static __device__ __forceinline__ void sts64(uint32_t a, uint32_t v0, uint32_t v1) {
    asm volatile("st.shared.v2.b32 [%0], {%1,%2};" :: "r"(a), "r"(v0), "r"(v1));
}
static __device__ __forceinline__ void sts128z(uint32_t a) {
    asm volatile("st.shared.v4.b32 [%0], {%1,%1,%1,%1};" :: "r"(a), "r"(0u));
}
static __device__ __forceinline__ void cp16(uint32_t saddr, const void* g) {
    asm volatile("{ .reg .u64 gp; cvta.to.global.u64 gp, %1;"
                 "  cp.async.cg.shared.global [%0], [gp], 16; }"
                 :: "r"(saddr), "l"(g) : "memory");
}
#define CP_COMMIT() asm volatile("cp.async.commit_group;" ::: "memory")
#define CP_WAIT1()  asm volatile("cp.async.wait_group 1;" ::: "memory")
#define CP_WAIT0()  asm volatile("cp.async.wait_group 0;" ::: "memory")

static __device__ __forceinline__ void mma4(float* c, const uint4& a, uint32_t b0, uint32_t b1) {
    asm volatile(
        "mma.sync.aligned.m16n8k16.row.col.f32.f16.f16.f32 "
        "{%0,%1,%2,%3}, {%4,%5,%6,%7}, {%8,%9}, {%0,%1,%2,%3};"
        : "+f"(c[0]), "+f"(c[1]), "+f"(c[2]), "+f"(c[3])
        : "r"(a.x), "r"(a.y), "r"(a.z), "r"(a.w), "r"(b0), "r"(b1));
}
static __device__ __forceinline__ float tanhA(float x) {
    float y;
    asm("tanh.approx.f32 %0, %1;" : "=f"(y) : "f"(x));
    return y;
}
static __device__ __forceinline__ float sigA(float x) {
    return fmaf(tanhA(0.5f * x), 0.5f, 0.5f);
}
static __device__ __forceinline__ uint32_t packh2(float v0, float v1) {
    __half2 h = __floats2half2_rn(v0, v1);
    return *reinterpret_cast<uint32_t*>(&h);
}
static __device__ __forceinline__ void ffma2(ull& c, ull a, ull b) {
    asm("fma.rn.f32x2 %0, %1, %2, %0;" : "+l"(c) : "l"(a), "l"(b));
}
static __device__ __forceinline__ ull pack2f(float x, float y) {
    ull r;
    asm("mov.b64 %0, {%1, %2};" : "=l"(r)
        : "r"(__float_as_uint(x)), "r"(__float_as_uint(y)));
    return r;
}
static __device__ __forceinline__ float2 unpk2f(ull v) {
    unsigned int lo, hi;
    asm("mov.b64 {%0, %1}, %2;" : "=r"(lo), "=r"(hi) : "l"(v));
    return make_float2(__uint_as_float(lo), __uint_as_float(hi));
}

#define MMA6(accp, A, B0, B1, B2) \
    mma4((accp) + 0,  A, B0.x, B0.y); mma4((accp) + 4,  A, B0.z, B0.w); \
    mma4((accp) + 8,  A, B1.x, B1.y); mma4((accp) + 12, A, B1.z, B1.w); \
    mma4((accp) + 16, A, B2.x, B2.y); mma4((accp) + 20, A, B2.z, B2.w);

// one 6-kt chunk, single fp16 pass; warp covers 2 mtiles x 6 ntiles
static __device__ __forceinline__ void chunk_mma(uint32_t abA, uint32_t bb,
                                                 uint32_t aoffb, uint32_t boffb, float* acc) {
#pragma unroll
    for (int kt = 0; kt < 6; ++kt) {
        uint32_t aa = abA + kt * 4096 + aoffb;
        uint4 a0 = lds128(aa), a1 = lds128(aa + 512);
        uint32_t bo = kt * 3584 + boffb;
        uint4 B0 = lds128(bb + bo), B1 = lds128(bb + bo + 16), B2 = lds128(bb + bo + 32);
        MMA6(acc,      a0, B0, B1, B2);
        MMA6(acc + 24, a1, B0, B1, B2);
    }
}

// ===== prep: pack fp16 weights (bias folded) into frag-major images =====
__global__ void prep_kernel(const float* __restrict__ eW, const float* __restrict__ eb1,
                            const float* __restrict__ eb2, const float* __restrict__ dW,
                            const float* __restrict__ db1, const float* __restrict__ db2) {
    int idx = blockIdx.x * 256 + threadIdx.x;
    const int goff[3] = {0, 180, 270};  // i, g, o (f gate skipped: c0 = 0)
    if (idx < 3 * 96 * 96) {
        int gate = idx / (96 * 96), rem = idx % (96 * 96);
        int n = rem / 96, kp = rem % 96;
        int k = 2 * kp;
        float v0 = 0.f, v1 = 0.f;
        if (n < NH) {
            if (k < NF) { v0 = eW[(goff[gate] + n) * NF + k]; v1 = eW[(goff[gate] + n) * NF + k + 1]; }
            else if (k == NF) v0 = eb1[goff[gate] + n] + eb2[goff[gate] + n];
        }
        int pos = ((kp >> 3) * 32 + ((n & 7) << 2) + (kp & 3)) * 28 + (n >> 3) * 2 + ((kp >> 2) & 1);
        g_eBF[gate * EB_G + pos] = packh2(v0, v1);
        return;
    }
    int j = idx - 3 * 96 * 96;
    if (j < 3 * 96 * 48) {
        int gate = j / (96 * 48), rem = j % (96 * 48);
        int n = rem / 48, kp = rem % 48;
        int k = 2 * kp;
        float v0 = 0.f, v1 = 0.f;
        if (n < NH) {
            if (k < NH) { v0 = dW[(goff[gate] + n) * NH + k]; v1 = dW[(goff[gate] + n) * NH + k + 1]; }
            else if (k == NH) v0 = db1[goff[gate] + n] + db2[goff[gate] + n];
        }
        int pos = ((kp >> 3) * 32 + ((n & 7) << 2) + (kp & 3)) * 28 + (n >> 3) * 2 + ((kp >> 2) & 1);
        g_dBF[gate * DB_G + pos] = packh2(v0, v1);
    }
}

// ===== fused LSTM: single-pass fp16 mma.sync, 2 CTAs/SM =====
__global__ void __launch_bounds__(256, 2)
lstm_mma_kernel(const float* __restrict__ x) {
    extern __shared__ char smem[];
    const uint32_t sb = smem_u32(smem);
    const int tid = threadIdx.x, wid = tid >> 5, lane = tid & 31;
    const int b = blockIdx.x >> 1, th = blockIdx.x & 1;
    const int t0 = th * 120;
    const int tig = lane & 3, q = lane >> 2;
    const int mg = wid >> 1, ng = wid & 1;
    const uint32_t aoffb = (uint32_t)(mg * 2 * 512 + lane * 16);
    const uint32_t boffb = (uint32_t)(lane * 112 + ng * 48);

    // zero enc A region (49152B)
    for (int i = tid; i < 3072; i += 256) sts128z(sb + (uint32_t)(i * 16));

    // stage x coalesced, scatter fp16 into enc A frags (two 90-feature phases)
    float* Sx = reinterpret_cast<float*>(smem + OFF_B);
    for (int ph = 0; ph < 2; ++ph) {
        __syncthreads();
        const float* xb = x + ((size_t)b * NF + ph * 90) * NT + t0;
        for (int i = tid; i < 2700; i += 256) {
            int f = i / 30, c = i % 30;
            const float4 v = *reinterpret_cast<const float4*>(xb + f * NT + c * 4);
            *reinterpret_cast<float4*>(Sx + f * 120 + c * 4) = v;
        }
        __syncthreads();
        for (int i = tid; i < 5400; i += 256) {
            int r = i / 45, kpl = i % 45;
            int kp = ph * 45 + kpl, fp = 2 * kpl;
            uint32_t hv = packh2(Sx[fp * 120 + r], Sx[(fp + 1) * 120 + r]);
            int rr = r & 15, mt = r >> 4;
            int lne = ((rr & 7) << 2) | (kp & 3);
            int reg = (((kp >> 2) & 1) << 1) | (rr >> 3);
            uint32_t woff = (uint32_t)(((((kp >> 3) * 8 + mt) * 32 + lne) * 4 + reg) * 4);
            sts32(sb + OFF_AH + woff, hv);
        }
    }
    // enc bias column (k=180 -> kt 11, lane k-part 2, regs 0&1): fp16 1.0
    if (tid < 64) {
        int mt = tid >> 3, qq = tid & 7;
        uint32_t addr = sb + OFF_AH + (uint32_t)((((11 * 8 + mt) * 32 + ((qq << 2) | 2)) * 4) * 4);
        sts64(addr, 0x00003C00u, 0x00003C00u);
    }
    __syncthreads();  // Sx readers done before prefetch overwrites B region

    auto src = [&](int c) -> const uint4* {
        if (c < 6) return reinterpret_cast<const uint4*>(g_eBF + (c >> 1) * EB_G + (c & 1) * 5376);
        return reinterpret_cast<const uint4*>(g_dBF + (c - 6) * DB_G);
    };
    auto prefetch = [&](int c) {
        uint32_t d = sb + OFF_B + (uint32_t)((c & 1) * CHUNK_B);
        const uint4* s = src(c);
        for (int i = tid; i < 1344; i += 256) cp16(d + (uint32_t)(i * 16), s + i);
        CP_COMMIT();
    };

    prefetch(0);
    prefetch(1);

    float acc[48], sv[48];

    for (int c = 0; c < 9; ++c) {
        if (c < 8) { CP_WAIT1(); } else { CP_WAIT0(); }
        __syncthreads();  // chunk c visible; prior epilogue smem writes visible

        if (c == 0 || c == 2 || c == 4 || c >= 6) {
#pragma unroll
            for (int i = 0; i < 48; ++i) acc[i] = 0.f;
        }
        uint32_t abA = (c < 6) ? (sb + OFF_AH + (uint32_t)((c & 1) * 24576))
                               : (sb + OFF_ADH);
        uint32_t bb = sb + OFF_B + (uint32_t)((c & 1) * CHUNK_B);
        chunk_mma(abA, bb, aoffb, boffb, acc);

        if (c == 5) __syncthreads();  // all enc-A readers done before dec-A scatter

        // epilogues
        if (c == 1 || c == 6) {
#pragma unroll
            for (int i = 0; i < 48; ++i) sv[i] = sigA(acc[i]);
        } else if (c == 3 || c == 7) {
#pragma unroll
            for (int i = 0; i < 48; ++i) sv[i] = sv[i] * tanhA(acc[i]);  // c-state
        } else if (c == 5) {
            // h1 = sig(sig(o)*tanh(c)) -> scatter fp16 into dec A frags (own-lane writes)
#pragma unroll
            for (int mi = 0; mi < 2; ++mi) {
#pragma unroll
                for (int ni = 0; ni < 6; ++ni) {
                    const float* a = acc + (mi * 6 + ni) * 4;
                    const float* s = sv + (mi * 6 + ni) * 4;
                    int nt = ng * 6 + ni;
                    uint32_t hv1, hv2;
                    if (nt == 11 && tig >= 1) {
                        hv1 = hv2 = (tig == 1) ? 0x00003C00u : 0u;  // dec bias col j=90
                    } else {
                        hv1 = packh2(sigA(sigA(a[0]) * tanhA(s[0])),
                                     sigA(sigA(a[1]) * tanhA(s[1])));
                        hv2 = packh2(sigA(sigA(a[2]) * tanhA(s[2])),
                                     sigA(sigA(a[3]) * tanhA(s[3])));
                    }
                    int jp = nt * 4 + tig;
                    int ktd = jp >> 3, regb = ((jp >> 2) & 1) << 1;
                    int mtd = mg * 2 + mi;
                    uint32_t w = sb + OFF_ADH +
                        (uint32_t)(((((ktd * 8 + mtd) * 32 + lane) * 4) + regb) * 4);
                    sts64(w, hv1, hv2);
                }
            }
        } else if (c == 8) {
            // h2 = sig(o)*tanh(c) -> g_h2h (fp16)
            __half* hb = g_h2h + (size_t)b * (NT * NH) + (size_t)t0 * NH;
#pragma unroll
            for (int mi = 0; mi < 2; ++mi) {
#pragma unroll
                for (int ni = 0; ni < 6; ++ni) {
                    int nt = ng * 6 + ni;
                    if (nt == 11 && tig >= 1) continue;
                    const float* a = acc + (mi * 6 + ni) * 4;
                    const float* s = sv + (mi * 6 + ni) * 4;
                    int j0 = nt * 8 + 2 * tig;
                    int r1 = (mg * 2 + mi) * 16 + q, r2 = r1 + 8;
                    uint32_t p1 = packh2(sigA(a[0]) * tanhA(s[0]),
                                         sigA(a[1]) * tanhA(s[1]));
                    *reinterpret_cast<uint32_t*>(hb + r1 * NH + j0) = p1;
                    if (r2 < 120) {
                        uint32_t p2 = packh2(sigA(a[2]) * tanhA(s[2]),
                                             sigA(a[3]) * tanhA(s[3]));
                        *reinterpret_cast<uint32_t*>(hb + r2 * NH + j0) = p2;
                    }
                }
            }
        }

        __syncthreads();  // buf[c&1] readers done; epilogue smem writes published
        if (c + 2 < 9) prefetch(c + 2);
    }
}

// ===== output GEMM (k-split partials, h2 fp16, f32x2 FMA) =====
__global__ void __launch_bounds__(256, 1)
out_gemm_kernel(const float* __restrict__ W) {
    extern __shared__ float sm[];
    float* Hs = sm;           // 240*33
    float* Wt = sm + 7920;    // 240*44
    const int b0 = blockIdx.y * 32;
    const int k0 = blockIdx.x * (21600 / KS);
    const int tid = threadIdx.x, wi = tid >> 5, lane = tid & 31;

    ull acc[20];
#pragma unroll
    for (int n = 0; n < 20; ++n) acc[n] = 0ull;

    for (int tile = 0; tile < (21600 / KS) / 240; ++tile) {
        const int kt = k0 + tile * 240;
        __syncthreads();
        for (int idx = tid; idx < 32 * 120; idx += 256) {
            int bb = idx / 120, k2 = idx - bb * 120;
            __half2 h = *reinterpret_cast<const __half2*>(
                g_h2h + (size_t)(b0 + bb) * 21600 + kt + 2 * k2);
            float2 f = __half22float2(h);
            Hs[(2 * k2) * 33 + bb] = f.x;
            Hs[(2 * k2 + 1) * 33 + bb] = f.y;
        }
        for (int idx = tid; idx < 40 * 240; idx += 256) {
            int n = idx / 240, k = idx - n * 240;
            Wt[k * 44 + n] = W[(size_t)n * 21600 + kt + k];
        }
        __syncthreads();
#pragma unroll 2
        for (int kk = 0; kk < 30; ++kk) {
            int k = wi * 30 + kk;
            float h = Hs[k * 33 + lane];
            ull hh = pack2f(h, h);
            const ull* wp = reinterpret_cast<const ull*>(Wt + k * 44);
#pragma unroll
            for (int n2 = 0; n2 < 20; ++n2) ffma2(acc[n2], hh, wp[n2]);
        }
    }
    __syncthreads();
    float* Rs = sm;
#pragma unroll
    for (int n2 = 0; n2 < 20; ++n2) {
        float2 v = unpk2f(acc[n2]);
        Rs[(wi * 32 + lane) * 40 + 2 * n2] = v.x;
        Rs[(wi * 32 + lane) * 40 + 2 * n2 + 1] = v.y;
    }
    __syncthreads();
    for (int idx = tid; idx < 32 * 40; idx += 256) {
        int bb = idx / 40, n = idx - bb * 40;
        float s = 0.f;
#pragma unroll
        for (int w = 0; w < 8; ++w) s += Rs[(w * 32 + bb) * 40 + n];
        g_part[blockIdx.x * (NB * 40) + (b0 + bb) * 40 + n] = s;
    }
}

__global__ void softmax_kernel(const float* __restrict__ ob, float* __restrict__ out) {
    __shared__ float L[40];
    __shared__ float E[40];
    const int b = blockIdx.x, n = threadIdx.x;
    float s = 0.f;
#pragma unroll
    for (int ks = 0; ks < KS; ++ks) s += g_part[ks * (NB * 40) + b * 40 + n];
    s += ob[n];
    L[n] = s;
    __syncthreads();
    const int g0 = (n / 10) * 10;
    float mx = -1e30f;
#pragma unroll
    for (int i = 0; i < 10; ++i) mx = fmaxf(mx, L[g0 + i]);
    float e = __expf(s - mx);
    E[n] = e;
    __syncthreads();
    float sum = 0.f;
#pragma unroll
    for (int i = 0; i < 10; ++i) sum += E[g0 + i];
    out[b * 40 + n] = __fdividef(e, sum);
}

extern "C" void kernel_launch(void* const* d_in, const int* in_sizes, int n_in,
                              void* d_out, int out_size) {
    const float* x   = (const float*)d_in[0];
    const float* eW  = (const float*)d_in[1];
    const float* eb1 = (const float*)d_in[2];
    const float* eb2 = (const float*)d_in[3];
    const float* dW  = (const float*)d_in[4];
    const float* db1 = (const float*)d_in[5];
    const float* db2 = (const float*)d_in[6];
    const float* oW  = (const float*)d_in[7];
    const float* ob  = (const float*)d_in[8];
    float* out = (float*)d_out;

    cudaFuncSetAttribute(lstm_mma_kernel,
                         cudaFuncAttributeMaxDynamicSharedMemorySize, SMEM_LSTM);
    cudaFuncSetAttribute(out_gemm_kernel,
                         cudaFuncAttributeMaxDynamicSharedMemorySize, 73920);

    prep_kernel<<<162, 256>>>(eW, eb1, eb2, dW, db1, db2);
    lstm_mma_kernel<<<2048, 256, SMEM_LSTM>>>(x);
    out_gemm_kernel<<<dim3(KS, 32), 256, 73920>>>(oW);
    softmax_kernel<<<NB, 40>>>(ob, out);
}

// round 10
// speedup vs baseline: 4.0373x; 1.0053x over previous
#include <cuda_runtime.h>
#include <cuda_fp16.h>
#include <cstdint>

#define NB 1024
#define NT 240
#define NH 90
#define NF 180
#define KS 30

typedef unsigned long long ull;

// frag-image sizes (u32 words)
#define EB_G (12*32*28)  // enc gate image
#define DB_G (6*32*28)   // dec gate image

// lstm smem layout (bytes)
#define OFF_AH  0        // enc A fp16 [12kt][8mt][32][16B] = 49152
#define OFF_ADH 0        // dec A fp16 [6kt][8][32][16B] = 24576 (reuse)
#define OFF_B   49152    // 2 x 21504 chunk buffers
#define CHUNK_B 21504
#define SMEM_LSTM (OFF_B + 43200)   // 92352: x staging needs 43200B

__device__ __align__(16) uint32_t g_eBF[3*EB_G];
__device__ __align__(16) uint32_t g_dBF[3*DB_G];
__device__ __half g_h2h[(size_t)NB*NT*NH];
__device__ float g_part[KS*NB*40];

// ---- helpers ----
static __device__ __forceinline__ uint32_t smem_u32(const void* p) {
    uint32_t a;
    asm("{ .reg .u64 t; cvta.to.shared.u64 t, %1; cvt.u32.u64 %0, t; }" : "=r"(a) : "l"(p));
    return a;
}
static __device__ __forceinline__ uint4 lds128(uint32_t a) {
    uint4 v;
    asm volatile("ld.shared.v4.b32 {%0,%1,%2,%3}, [%4];"
                 : "=r"(v.x), "=r"(v.y), "=r"(v.z), "=r"(v.w) : "r"(a));
    return v;
}
static __device__ __forceinline__ void sts32(uint32_t a, uint32_t v) {
    asm volatile("st.shared.b32 [%0], %1;" :: "r"(a), "r"(v));
}
static __device__ __forceinline__ void sts64(uint32_t a, uint32_t v0, uint32_t v1) {
    asm volatile("st.shared.v2.b32 [%0], {%1,%2};" :: "r"(a), "r"(v0), "r"(v1));
}
static __device__ __forceinline__ void sts128z(uint32_t a) {
    asm volatile("st.shared.v4.b32 [%0], {%1,%1,%1,%1};" :: "r"(a), "r"(0u));
}
static __device__ __forceinline__ void cp16(uint32_t saddr, const void* g) {
    asm volatile("{ .reg .u64 gp; cvta.to.global.u64 gp, %1;"
                 "  cp.async.cg.shared.global [%0], [gp], 16; }"
                 :: "r"(saddr), "l"(g) : "memory");
}
#define CP_COMMIT() asm volatile("cp.async.commit_group;" ::: "memory")
#define CP_WAIT1()  asm volatile("cp.async.wait_group 1;" ::: "memory")
#define CP_WAIT0()  asm volatile("cp.async.wait_group 0;" ::: "memory")

static __device__ __forceinline__ void mma4(float* c, const uint4& a, uint32_t b0, uint32_t b1) {
    asm volatile(
        "mma.sync.aligned.m16n8k16.row.col.f32.f16.f16.f32 "
        "{%0,%1,%2,%3}, {%4,%5,%6,%7}, {%8,%9}, {%0,%1,%2,%3};"
        : "+f"(c[0]), "+f"(c[1]), "+f"(c[2]), "+f"(c[3])
        : "r"(a.x), "r"(a.y), "r"(a.z), "r"(a.w), "r"(b0), "r"(b1));
}
static __device__ __forceinline__ float tanhA(float x) {
    float y;
    asm("tanh.approx.f32 %0, %1;" : "=f"(y) : "f"(x));
    return y;
}
static __device__ __forceinline__ float sigA(float x) {
    return fmaf(tanhA(0.5f * x), 0.5f, 0.5f);
}
static __device__ __forceinline__ uint32_t packh2(float v0, float v1) {
    __half2 h = __floats2half2_rn(v0, v1);
    return *reinterpret_cast<uint32_t*>(&h);
}
static __device__ __forceinline__ float2 unpkh2(uint32_t v) {
    __half2 h = *reinterpret_cast<__half2*>(&v);
    return __half22float2(h);
}
static __device__ __forceinline__ void ffma2(ull& c, ull a, ull b) {
    asm("fma.rn.f32x2 %0, %1, %2, %0;" : "+l"(c) : "l"(a), "l"(b));
}
static __device__ __forceinline__ ull pack2f(float x, float y) {
    ull r;
    asm("mov.b64 %0, {%1, %2};" : "=l"(r)
        : "r"(__float_as_uint(x)), "r"(__float_as_uint(y)));
    return r;
}
static __device__ __forceinline__ float2 unpk2f(ull v) {
    unsigned int lo, hi;
    asm("mov.b64 {%0, %1}, %2;" : "=r"(lo), "=r"(hi) : "l"(v));
    return make_float2(__uint_as_float(lo), __uint_as_float(hi));
}

#define MMA6(accp, A, B0, B1, B2) \
    mma4((accp) + 0,  A, B0.x, B0.y); mma4((accp) + 4,  A, B0.z, B0.w); \
    mma4((accp) + 8,  A, B1.x, B1.y); mma4((accp) + 12, A, B1.z, B1.w); \
    mma4((accp) + 16, A, B2.x, B2.y); mma4((accp) + 20, A, B2.z, B2.w);

// one 6-kt chunk, single fp16 pass; warp covers 2 mtiles x 6 ntiles
static __device__ __forceinline__ void chunk_mma(uint32_t abA, uint32_t bb,
                                                 uint32_t aoffb, uint32_t boffb, float* acc) {
#pragma unroll
    for (int kt = 0; kt < 6; ++kt) {
        uint32_t aa = abA + kt * 4096 + aoffb;
        uint4 a0 = lds128(aa), a1 = lds128(aa + 512);
        uint32_t bo = kt * 3584 + boffb;
        uint4 B0 = lds128(bb + bo), B1 = lds128(bb + bo + 16), B2 = lds128(bb + bo + 32);
        MMA6(acc,      a0, B0, B1, B2);
        MMA6(acc + 24, a1, B0, B1, B2);
    }
}

// ===== prep: pack fp16 weights (bias folded) into frag-major images =====
__global__ void prep_kernel(const float* __restrict__ eW, const float* __restrict__ eb1,
                            const float* __restrict__ eb2, const float* __restrict__ dW,
                            const float* __restrict__ db1, const float* __restrict__ db2) {
    int idx = blockIdx.x * 256 + threadIdx.x;
    const int goff[3] = {0, 180, 270};  // i, g, o (f gate skipped: c0 = 0)
    if (idx < 3 * 96 * 96) {
        int gate = idx / (96 * 96), rem = idx % (96 * 96);
        int n = rem / 96, kp = rem % 96;
        int k = 2 * kp;
        float v0 = 0.f, v1 = 0.f;
        if (n < NH) {
            if (k < NF) { v0 = eW[(goff[gate] + n) * NF + k]; v1 = eW[(goff[gate] + n) * NF + k + 1]; }
            else if (k == NF) v0 = eb1[goff[gate] + n] + eb2[goff[gate] + n];
        }
        int pos = ((kp >> 3) * 32 + ((n & 7) << 2) + (kp & 3)) * 28 + (n >> 3) * 2 + ((kp >> 2) & 1);
        g_eBF[gate * EB_G + pos] = packh2(v0, v1);
        return;
    }
    int j = idx - 3 * 96 * 96;
    if (j < 3 * 96 * 48) {
        int gate = j / (96 * 48), rem = j % (96 * 48);
        int n = rem / 48, kp = rem % 48;
        int k = 2 * kp;
        float v0 = 0.f, v1 = 0.f;
        if (n < NH) {
            if (k < NH) { v0 = dW[(goff[gate] + n) * NH + k]; v1 = dW[(goff[gate] + n) * NH + k + 1]; }
            else if (k == NH) v0 = db1[goff[gate] + n] + db2[goff[gate] + n];
        }
        int pos = ((kp >> 3) * 32 + ((n & 7) << 2) + (kp & 3)) * 28 + (n >> 3) * 2 + ((kp >> 2) & 1);
        g_dBF[gate * DB_G + pos] = packh2(v0, v1);
    }
}

// ===== fused LSTM: single-pass fp16 mma.sync, 2 CTAs/SM, packed fp16 carry =====
__global__ void __launch_bounds__(256, 2)
lstm_mma_kernel(const float* __restrict__ x) {
    extern __shared__ char smem[];
    const uint32_t sb = smem_u32(smem);
    const int tid = threadIdx.x, wid = tid >> 5, lane = tid & 31;
    const int b = blockIdx.x >> 1, th = blockIdx.x & 1;
    const int t0 = th * 120;
    const int tig = lane & 3, q = lane >> 2;
    const int mg = wid >> 1, ng = wid & 1;
    const uint32_t aoffb = (uint32_t)(mg * 2 * 512 + lane * 16);
    const uint32_t boffb = (uint32_t)(lane * 112 + ng * 48);

    // zero enc A region (49152B)
    for (int i = tid; i < 3072; i += 256) sts128z(sb + (uint32_t)(i * 16));

    // stage x coalesced, scatter fp16 into enc A frags (two 90-feature phases)
    float* Sx = reinterpret_cast<float*>(smem + OFF_B);
    for (int ph = 0; ph < 2; ++ph) {
        __syncthreads();
        const float* xb = x + ((size_t)b * NF + ph * 90) * NT + t0;
        for (int i = tid; i < 2700; i += 256) {
            int f = i / 30, c = i % 30;
            const float4 v = *reinterpret_cast<const float4*>(xb + f * NT + c * 4);
            *reinterpret_cast<float4*>(Sx + f * 120 + c * 4) = v;
        }
        __syncthreads();
        for (int i = tid; i < 5400; i += 256) {
            int r = i / 45, kpl = i % 45;
            int kp = ph * 45 + kpl, fp = 2 * kpl;
            uint32_t hv = packh2(Sx[fp * 120 + r], Sx[(fp + 1) * 120 + r]);
            int rr = r & 15, mt = r >> 4;
            int lne = ((rr & 7) << 2) | (kp & 3);
            int reg = (((kp >> 2) & 1) << 1) | (rr >> 3);
            uint32_t woff = (uint32_t)(((((kp >> 3) * 8 + mt) * 32 + lne) * 4 + reg) * 4);
            sts32(sb + OFF_AH + woff, hv);
        }
    }
    // enc bias column (k=180 -> kt 11, lane k-part 2, regs 0&1): fp16 1.0
    if (tid < 64) {
        int mt = tid >> 3, qq = tid & 7;
        uint32_t addr = sb + OFF_AH + (uint32_t)((((11 * 8 + mt) * 32 + ((qq << 2) | 2)) * 4) * 4);
        sts64(addr, 0x00003C00u, 0x00003C00u);
    }
    __syncthreads();  // Sx readers done before prefetch overwrites B region

    auto src = [&](int c) -> const uint4* {
        if (c < 6) return reinterpret_cast<const uint4*>(g_eBF + (c >> 1) * EB_G + (c & 1) * 5376);
        return reinterpret_cast<const uint4*>(g_dBF + (c - 6) * DB_G);
    };
    auto prefetch = [&](int c) {
        uint32_t d = sb + OFF_B + (uint32_t)((c & 1) * CHUNK_B);
        const uint4* s = src(c);
        for (int i = tid; i < 1344; i += 256) cp16(d + (uint32_t)(i * 16), s + i);
        CP_COMMIT();
    };

    prefetch(0);
    prefetch(1);

    float acc[48];
    uint32_t svp[24];   // packed fp16 gate-state carry (sig(i), then c)

    for (int c = 0; c < 9; ++c) {
        if (c < 8) { CP_WAIT1(); } else { CP_WAIT0(); }
        __syncthreads();  // chunk c visible; prior epilogue smem writes visible

        if (c == 0 || c == 2 || c == 4 || c >= 6) {
#pragma unroll
            for (int i = 0; i < 48; ++i) acc[i] = 0.f;
        }
        uint32_t abA = (c < 6) ? (sb + OFF_AH + (uint32_t)((c & 1) * 24576))
                               : (sb + OFF_ADH);
        uint32_t bb = sb + OFF_B + (uint32_t)((c & 1) * CHUNK_B);
        chunk_mma(abA, bb, aoffb, boffb, acc);

        if (c == 5) __syncthreads();  // all enc-A readers done before dec-A scatter

        // epilogues
        if (c == 1 || c == 6) {
#pragma unroll
            for (int g = 0; g < 12; ++g) {
                svp[2 * g]     = packh2(sigA(acc[4 * g]),     sigA(acc[4 * g + 1]));
                svp[2 * g + 1] = packh2(sigA(acc[4 * g + 2]), sigA(acc[4 * g + 3]));
            }
        } else if (c == 3 || c == 7) {
#pragma unroll
            for (int g = 0; g < 12; ++g) {
                float2 s0 = unpkh2(svp[2 * g]), s1 = unpkh2(svp[2 * g + 1]);
                svp[2 * g]     = packh2(s0.x * tanhA(acc[4 * g]),
                                        s0.y * tanhA(acc[4 * g + 1]));
                svp[2 * g + 1] = packh2(s1.x * tanhA(acc[4 * g + 2]),
                                        s1.y * tanhA(acc[4 * g + 3]));
            }
        } else if (c == 5) {
            // h1 = sig(sig(o)*tanh(c)) -> scatter fp16 into dec A frags (own-lane writes)
#pragma unroll
            for (int mi = 0; mi < 2; ++mi) {
#pragma unroll
                for (int ni = 0; ni < 6; ++ni) {
                    int g = mi * 6 + ni;
                    const float* a = acc + g * 4;
                    int nt = ng * 6 + ni;
                    uint32_t hv1, hv2;
                    if (nt == 11 && tig >= 1) {
                        hv1 = hv2 = (tig == 1) ? 0x00003C00u : 0u;  // dec bias col j=90
                    } else {
                        float2 c0 = unpkh2(svp[2 * g]), c1 = unpkh2(svp[2 * g + 1]);
                        hv1 = packh2(sigA(sigA(a[0]) * tanhA(c0.x)),
                                     sigA(sigA(a[1]) * tanhA(c0.y)));
                        hv2 = packh2(sigA(sigA(a[2]) * tanhA(c1.x)),
                                     sigA(sigA(a[3]) * tanhA(c1.y)));
                    }
                    int jp = nt * 4 + tig;
                    int ktd = jp >> 3, regb = ((jp >> 2) & 1) << 1;
                    int mtd = mg * 2 + mi;
                    uint32_t w = sb + OFF_ADH +
                        (uint32_t)(((((ktd * 8 + mtd) * 32 + lane) * 4) + regb) * 4);
                    sts64(w, hv1, hv2);
                }
            }
        } else if (c == 8) {
            // h2 = sig(o)*tanh(c) -> g_h2h (fp16)
            __half* hb = g_h2h + (size_t)b * (NT * NH) + (size_t)t0 * NH;
#pragma unroll
            for (int mi = 0; mi < 2; ++mi) {
#pragma unroll
                for (int ni = 0; ni < 6; ++ni) {
                    int nt = ng * 6 + ni;
                    if (nt == 11 && tig >= 1) continue;
                    int g = mi * 6 + ni;
                    const float* a = acc + g * 4;
                    float2 c0 = unpkh2(svp[2 * g]), c1 = unpkh2(svp[2 * g + 1]);
                    int j0 = nt * 8 + 2 * tig;
                    int r1 = (mg * 2 + mi) * 16 + q, r2 = r1 + 8;
                    uint32_t p1 = packh2(sigA(a[0]) * tanhA(c0.x),
                                         sigA(a[1]) * tanhA(c0.y));
                    *reinterpret_cast<uint32_t*>(hb + r1 * NH + j0) = p1;
                    if (r2 < 120) {
                        uint32_t p2 = packh2(sigA(a[2]) * tanhA(c1.x),
                                             sigA(a[3]) * tanhA(c1.y));
                        *reinterpret_cast<uint32_t*>(hb + r2 * NH + j0) = p2;
                    }
                }
            }
        }

        __syncthreads();  // buf[c&1] readers done; epilogue smem writes published
        if (c + 2 < 9) prefetch(c + 2);
    }
}

// ===== output GEMM (k-split partials, h2 fp16, f32x2 FMA) =====
__global__ void __launch_bounds__(256, 1)
out_gemm_kernel(const float* __restrict__ W) {
    extern __shared__ float sm[];
    float* Hs = sm;           // 240*33
    float* Wt = sm + 7920;    // 240*44
    const int b0 = blockIdx.y * 32;
    const int k0 = blockIdx.x * (21600 / KS);
    const int tid = threadIdx.x, wi = tid >> 5, lane = tid & 31;

    ull acc[20];
#pragma unroll
    for (int n = 0; n < 20; ++n) acc[n] = 0ull;

    for (int tile = 0; tile < (21600 / KS) / 240; ++tile) {
        const int kt = k0 + tile * 240;
        __syncthreads();
        for (int idx = tid; idx < 32 * 120; idx += 256) {
            int bb = idx / 120, k2 = idx - bb * 120;
            __half2 h = *reinterpret_cast<const __half2*>(
                g_h2h + (size_t)(b0 + bb) * 21600 + kt + 2 * k2);
            float2 f = __half22float2(h);
            Hs[(2 * k2) * 33 + bb] = f.x;
            Hs[(2 * k2 + 1) * 33 + bb] = f.y;
        }
        for (int idx = tid; idx < 40 * 240; idx += 256) {
            int n = idx / 240, k = idx - n * 240;
            Wt[k * 44 + n] = W[(size_t)n * 21600 + kt + k];
        }
        __syncthreads();
#pragma unroll 2
        for (int kk = 0; kk < 30; ++kk) {
            int k = wi * 30 + kk;
            float h = Hs[k * 33 + lane];
            ull hh = pack2f(h, h);
            const ull* wp = reinterpret_cast<const ull*>(Wt + k * 44);
#pragma unroll
            for (int n2 = 0; n2 < 20; ++n2) ffma2(acc[n2], hh, wp[n2]);
        }
    }
    __syncthreads();
    float* Rs = sm;
#pragma unroll
    for (int n2 = 0; n2 < 20; ++n2) {
        float2 v = unpk2f(acc[n2]);
        Rs[(wi * 32 + lane) * 40 + 2 * n2] = v.x;
        Rs[(wi * 32 + lane) * 40 + 2 * n2 + 1] = v.y;
    }
    __syncthreads();
    for (int idx = tid; idx < 32 * 40; idx += 256) {
        int bb = idx / 40, n = idx - bb * 40;
        float s = 0.f;
#pragma unroll
        for (int w = 0; w < 8; ++w) s += Rs[(w * 32 + bb) * 40 + n];
        g_part[blockIdx.x * (NB * 40) + (b0 + bb) * 40 + n] = s;
    }
}

__global__ void softmax_kernel(const float* __restrict__ ob, float* __restrict__ out) {
    __shared__ float L[40];
    __shared__ float E[40];
    const int b = blockIdx.x, n = threadIdx.x;
    float s = 0.f;
#pragma unroll
    for (int ks = 0; ks < KS; ++ks) s += g_part[ks * (NB * 40) + b * 40 + n];
    s += ob[n];
    L[n] = s;
    __syncthreads();
    const int g0 = (n / 10) * 10;
    float mx = -1e30f;
#pragma unroll
    for (int i = 0; i < 10; ++i) mx = fmaxf(mx, L[g0 + i]);
    float e = __expf(s - mx);
    E[n] = e;
    __syncthreads();
    float sum = 0.f;
#pragma unroll
    for (int i = 0; i < 10; ++i) sum += E[g0 + i];
    out[b * 40 + n] = __fdividef(e, sum);
}

extern "C" void kernel_launch(void* const* d_in, const int* in_sizes, int n_in,
                              void* d_out, int out_size) {
    const float* x   = (const float*)d_in[0];
    const float* eW  = (const float*)d_in[1];
    const float* eb1 = (const float*)d_in[2];
    const float* eb2 = (const float*)d_in[3];
    const float* dW  = (const float*)d_in[4];
    const float* db1 = (const float*)d_in[5];
    const float* db2 = (const float*)d_in[6];
    const float* oW  = (const float*)d_in[7];
    const float* ob  = (const float*)d_in[8];
    float* out = (float*)d_out;

    cudaFuncSetAttribute(lstm_mma_kernel,
                         cudaFuncAttributeMaxDynamicSharedMemorySize, SMEM_LSTM);
    cudaFuncSetAttribute(out_gemm_kernel,
                         cudaFuncAttributeMaxDynamicSharedMemorySize, 73920);

    prep_kernel<<<162, 256>>>(eW, eb1, eb2, dW, db1, db2);
    lstm_mma_kernel<<<2048, 256, SMEM_LSTM>>>(x);
    out_gemm_kernel<<<dim3(KS, 32), 256, 73920>>>(oW);
    softmax_kernel<<<NB, 40>>>(ob, out);
}